// round 1
// baseline (speedup 1.0000x reference)
#include <cuda_runtime.h>
#include <cuda_bf16.h>
#include <cstdint>

// Problem constants
#define BB   8
#define SS   2048
#define DIMV 2048
#define HDV  128
#define MTOK (BB*SS)        // 16384 tokens

// Scratch (device globals: no allocation allowed)
__device__ float g_q[MTOK * HDV];
__device__ float g_k[MTOK * HDV];
__device__ float g_v[MTOK * HDV];
__device__ float g_y[MTOK * HDV];
__device__ float g_wfin_scratch[BB * HDV * HDV];

// ---------------------------------------------------------------------------
// Generic tiled SGEMM with bias:  O[M,N] = X[M,K] @ W[K,N] + bias[N]
// BM=64, BN=128, BK=8, 256 threads, each thread computes 4x8.
// ---------------------------------------------------------------------------
__global__ __launch_bounds__(256) void sgemm_bias(
    const float* __restrict__ X, const float* __restrict__ W,
    const float* __restrict__ bias, float* __restrict__ O,
    int M, int N, int K)
{
    const int BM = 64, BN = 128, BK = 8;
    __shared__ float As[BK][BM];
    __shared__ float Bs[BK][BN];

    const int m0 = blockIdx.x * BM;
    const int n0 = blockIdx.y * BN;
    const int t  = threadIdx.x;
    const int tx = t & 15;        // 0..15  (N direction, 8 cols each)
    const int ty = t >> 4;        // 0..15  (M direction, 4 rows each)

    float acc[4][8];
#pragma unroll
    for (int m = 0; m < 4; m++)
#pragma unroll
        for (int n = 0; n < 8; n++) acc[m][n] = 0.0f;

    for (int k0 = 0; k0 < K; k0 += BK) {
        // Load X tile (64x8) transposed into As[8][64]
#pragma unroll
        for (int i = 0; i < 2; i++) {
            int e = t + i * 256;
            int r = e >> 3, c = e & 7;
            As[c][r] = X[(size_t)(m0 + r) * K + (k0 + c)];
        }
        // Load W tile (8x128) into Bs
#pragma unroll
        for (int i = 0; i < 4; i++) {
            int e = t + i * 256;
            int r = e >> 7, c = e & 127;
            Bs[r][c] = W[(size_t)(k0 + r) * N + (n0 + c)];
        }
        __syncthreads();

#pragma unroll
        for (int kk = 0; kk < BK; kk++) {
            float4 a  = *reinterpret_cast<const float4*>(&As[kk][ty * 4]);
            float4 b0 = *reinterpret_cast<const float4*>(&Bs[kk][tx * 8]);
            float4 b1 = *reinterpret_cast<const float4*>(&Bs[kk][tx * 8 + 4]);
            float am[4] = {a.x, a.y, a.z, a.w};
            float bn[8] = {b0.x, b0.y, b0.z, b0.w, b1.x, b1.y, b1.z, b1.w};
#pragma unroll
            for (int m = 0; m < 4; m++)
#pragma unroll
                for (int n = 0; n < 8; n++)
                    acc[m][n] = fmaf(am[m], bn[n], acc[m][n]);
        }
        __syncthreads();
    }

#pragma unroll
    for (int m = 0; m < 4; m++) {
        int row = m0 + ty * 4 + m;
#pragma unroll
        for (int n = 0; n < 8; n++) {
            int col = n0 + tx * 8 + n;
            O[(size_t)row * N + col] = acc[m][n] + bias[col];
        }
    }
}

// ---------------------------------------------------------------------------
// Delta-rule scan. KEY INSIGHT: each row i of W evolves independently:
//   y_i    = dot(W_i, q_t)
//   err_i  = dot(W_i, k_t) - v_i
//   W_i   -= lr * err_i * k_t
// => 1024 independent row-chains (B*HD), one warp per row.
// Lane l owns W_i[4l..4l+3]. Next step's q/k/v are prefetched into registers
// before the shuffle-reduce so global latency overlaps the dependency chain.
// ---------------------------------------------------------------------------
__global__ __launch_bounds__(256) void titan_scan(
    const float* __restrict__ q, const float* __restrict__ k,
    const float* __restrict__ v, const float* __restrict__ state,
    const float* __restrict__ lr_ptr,
    float* __restrict__ ys, float* __restrict__ wfin)
{
    const int warp = threadIdx.x >> 5;
    const int lane = threadIdx.x & 31;
    const int gid  = blockIdx.x * 8 + warp;   // 0..1023 row-chain id
    const int b    = gid >> 7;                // batch
    const int i    = gid & 127;               // W row

    const float lr = *lr_ptr;

    const float* qb = q + (size_t)b * SS * HDV + lane * 4;
    const float* kb = k + (size_t)b * SS * HDV + lane * 4;
    const float* vb = v + (size_t)b * SS * HDV + i;
    float*       yb = ys + (size_t)b * SS * HDV + i;

    float4 w4 = *reinterpret_cast<const float4*>(
        state + ((size_t)b * HDV + i) * HDV + lane * 4);

    // Prime the pipeline
    float4 qc = *reinterpret_cast<const float4*>(qb);
    float4 kc = *reinterpret_cast<const float4*>(kb);
    float  vc = *vb;

    for (int s = 0; s < SS; s++) {
        float4 qn = qc, kn = kc;
        float  vn = vc;
        if (s + 1 < SS) {
            qn = *reinterpret_cast<const float4*>(qb + (size_t)(s + 1) * HDV);
            kn = *reinterpret_cast<const float4*>(kb + (size_t)(s + 1) * HDV);
            vn = vb[(size_t)(s + 1) * HDV];
        }

        float dq = w4.x * qc.x + w4.y * qc.y + w4.z * qc.z + w4.w * qc.w;
        float dk = w4.x * kc.x + w4.y * kc.y + w4.z * kc.z + w4.w * kc.w;
#pragma unroll
        for (int o = 16; o > 0; o >>= 1) {
            dq += __shfl_xor_sync(0xffffffffu, dq, o);
            dk += __shfl_xor_sync(0xffffffffu, dk, o);
        }

        if (lane == 0) yb[(size_t)s * HDV] = dq;

        float e = lr * (dk - vc);
        w4.x = fmaf(-e, kc.x, w4.x);
        w4.y = fmaf(-e, kc.y, w4.y);
        w4.z = fmaf(-e, kc.z, w4.z);
        w4.w = fmaf(-e, kc.w, w4.w);

        qc = qn; kc = kn; vc = vn;
    }

    *reinterpret_cast<float4*>(wfin + ((size_t)b * HDV + i) * HDV + lane * 4) = w4;
}

// ---------------------------------------------------------------------------
// Launch: 3 QKV GEMMs -> scan -> output GEMM. All graph-capturable,
// zero allocations (scratch = __device__ globals).
// ---------------------------------------------------------------------------
extern "C" void kernel_launch(void* const* d_in, const int* in_sizes, int n_in,
                              void* d_out, int out_size)
{
    const float* x     = (const float*)d_in[0];
    const float* state = (const float*)d_in[1];
    const float* Wq    = (const float*)d_in[2];
    const float* bq    = (const float*)d_in[3];
    const float* Wk    = (const float*)d_in[4];
    const float* bk    = (const float*)d_in[5];
    const float* Wv    = (const float*)d_in[6];
    const float* bv    = (const float*)d_in[7];
    const float* Wo    = (const float*)d_in[8];
    const float* bo    = (const float*)d_in[9];
    const float* lr    = (const float*)d_in[10];
    float* out = (float*)d_out;

    float *gq, *gk, *gv, *gy, *gws;
    cudaGetSymbolAddress((void**)&gq,  g_q);
    cudaGetSymbolAddress((void**)&gk,  g_k);
    cudaGetSymbolAddress((void**)&gv,  g_v);
    cudaGetSymbolAddress((void**)&gy,  g_y);
    cudaGetSymbolAddress((void**)&gws, g_wfin_scratch);

    const size_t out_elems  = (size_t)BB * SS * DIMV;           // 33554432
    const size_t wfin_elems = (size_t)BB * HDV * HDV;           // 131072
    float* wfin = ((size_t)out_size >= out_elems + wfin_elems)
                      ? (out + out_elems) : gws;

    dim3 blk(256);
    // QKV projections: M=16384, N=128, K=2048
    sgemm_bias<<<dim3(MTOK / 64, 1), blk>>>(x, Wq, bq, gq, MTOK, HDV, DIMV);
    sgemm_bias<<<dim3(MTOK / 64, 1), blk>>>(x, Wk, bk, gk, MTOK, HDV, DIMV);
    sgemm_bias<<<dim3(MTOK / 64, 1), blk>>>(x, Wv, bv, gv, MTOK, HDV, DIMV);

    // Delta-rule scan: 1024 row-chains, 8 warps per block
    titan_scan<<<128, 256>>>(gq, gk, gv, state, lr, gy, wfin);

    // Output projection: M=16384, N=2048, K=128
    sgemm_bias<<<dim3(MTOK / 64, DIMV / 128), blk>>>(gy, Wo, bo, out,
                                                     MTOK, DIMV, HDV);
}

// round 5
// speedup vs baseline: 1.4764x; 1.4764x over previous
#include <cuda_runtime.h>
#include <cuda_bf16.h>
#include <cstdint>

#define BB   8
#define SS   2048
#define DIMV 2048
#define HDV  128
#define MTOK (BB*SS)        // 16384 tokens
#define NQKV 384            // q|k|v concat width

// ---------------------------------------------------------------------------
// Scratch (device globals; no allocation allowed)
// ---------------------------------------------------------------------------
__device__ __nv_bfloat16 g_xh[MTOK * DIMV];
__device__ __nv_bfloat16 g_xm[MTOK * DIMV];
__device__ __nv_bfloat16 g_xl[MTOK * DIMV];
__device__ __nv_bfloat16 g_wqkvh[NQKV * DIMV];   // [384][2048] K-major
__device__ __nv_bfloat16 g_wqkvm[NQKV * DIMV];
__device__ __nv_bfloat16 g_wqkvl[NQKV * DIMV];
__device__ __nv_bfloat16 g_woh[DIMV * HDV];      // [2048][128] K-major
__device__ __nv_bfloat16 g_wol[DIMV * HDV];
__device__ float g_bqkv[NQKV];
__device__ float g_qkv[MTOK * NQKV];             // [token][384] = q|k|v
__device__ float g_y[MTOK * HDV];
__device__ __nv_bfloat16 g_yh[MTOK * HDV], g_yl[MTOK * HDV];
__device__ float g_wfin_scratch[BB * HDV * HDV];

// ---------------------------------------------------------------------------
// Helpers
// ---------------------------------------------------------------------------
__device__ __forceinline__ uint32_t smem_to_u32(const void* p) {
    uint32_t a;
    asm("{ .reg .u64 t; cvta.to.shared.u64 t, %1; cvt.u32.u64 %0, t; }"
        : "=r"(a) : "l"(p));
    return a;
}

#define SMEM_SWIZZLE_128B(off) ((off) ^ (((off) >> 3) & 0x70))

#define CP_ASYNC_CG(dst, src) \
    asm volatile("cp.async.cg.shared.global [%0], [%1], 16;" \
        :: "r"(dst), "l"(src) : "memory")
#define CP_COMMIT() asm volatile("cp.async.commit_group;" ::: "memory")
#define CP_WAIT_1() asm volatile("cp.async.wait_group 1;" ::: "memory")
#define CP_WAIT_0() asm volatile("cp.async.wait_group 0;" ::: "memory")

__device__ __forceinline__ void ldsm_x4(uint32_t (&r)[4], uint32_t addr) {
    asm volatile("ldmatrix.sync.aligned.m8n8.x4.shared.b16 {%0,%1,%2,%3}, [%4];"
        : "=r"(r[0]), "=r"(r[1]), "=r"(r[2]), "=r"(r[3]) : "r"(addr));
}

__device__ __forceinline__ void mma_bf16(float (&c)[4], const uint32_t (&a)[4],
                                         const uint32_t b0, const uint32_t b1) {
    asm volatile("mma.sync.aligned.m16n8k16.row.col.f32.bf16.bf16.f32 "
        "{%0,%1,%2,%3}, {%4,%5,%6,%7}, {%8,%9}, {%0,%1,%2,%3};"
        : "+f"(c[0]), "+f"(c[1]), "+f"(c[2]), "+f"(c[3])
        : "r"(a[0]), "r"(a[1]), "r"(a[2]), "r"(a[3]), "r"(b0), "r"(b1));
}

// ---------------------------------------------------------------------------
// fp32 -> bf16 splits
// ---------------------------------------------------------------------------
__device__ __forceinline__ void split2v(float x, unsigned short& h, unsigned short& l) {
    __nv_bfloat16 bh = __float2bfloat16(x);
    float r = x - __bfloat162float(bh);
    __nv_bfloat16 bl = __float2bfloat16(r);
    h = __bfloat16_as_ushort(bh);
    l = __bfloat16_as_ushort(bl);
}
__device__ __forceinline__ void split3v(float x, unsigned short& h,
                                        unsigned short& m, unsigned short& l) {
    __nv_bfloat16 bh = __float2bfloat16(x);
    float r = x - __bfloat162float(bh);
    __nv_bfloat16 bm = __float2bfloat16(r);
    float r2 = r - __bfloat162float(bm);
    __nv_bfloat16 bl = __float2bfloat16(r2);
    h = __bfloat16_as_ushort(bh);
    m = __bfloat16_as_ushort(bm);
    l = __bfloat16_as_ushort(bl);
}

__global__ __launch_bounds__(256) void split3_kernel(
    const float* __restrict__ in, __nv_bfloat16* __restrict__ h,
    __nv_bfloat16* __restrict__ m, __nv_bfloat16* __restrict__ l, int n4)
{
    int i = blockIdx.x * 256 + threadIdx.x;
    if (i >= n4) return;
    float4 x = reinterpret_cast<const float4*>(in)[i];
    ushort4 H, M, L;
    split3v(x.x, H.x, M.x, L.x);
    split3v(x.y, H.y, M.y, L.y);
    split3v(x.z, H.z, M.z, L.z);
    split3v(x.w, H.w, M.w, L.w);
    reinterpret_cast<ushort4*>(h)[i] = H;
    reinterpret_cast<ushort4*>(m)[i] = M;
    reinterpret_cast<ushort4*>(l)[i] = L;
}

__global__ __launch_bounds__(256) void split2_kernel(
    const float* __restrict__ in, __nv_bfloat16* __restrict__ h,
    __nv_bfloat16* __restrict__ l, int n4)
{
    int i = blockIdx.x * 256 + threadIdx.x;
    if (i >= n4) return;
    float4 x = reinterpret_cast<const float4*>(in)[i];
    ushort4 H, L;
    split2v(x.x, H.x, L.x);
    split2v(x.y, H.y, L.y);
    split2v(x.z, H.z, L.z);
    split2v(x.w, H.w, L.w);
    reinterpret_cast<ushort4*>(h)[i] = H;
    reinterpret_cast<ushort4*>(l)[i] = L;
}

// in [K,N] fp32 -> out [N,K] bf16 3-way
__global__ __launch_bounds__(256) void transpose_split3_kernel(
    const float* __restrict__ in, __nv_bfloat16* __restrict__ h,
    __nv_bfloat16* __restrict__ m, __nv_bfloat16* __restrict__ l, int K, int N)
{
    int idx = blockIdx.x * 256 + threadIdx.x;
    if (idx >= K * N) return;
    int k = idx / N, n = idx - k * N;
    unsigned short H, M, L;
    split3v(in[idx], H, M, L);
    size_t o = (size_t)n * K + k;
    h[o] = __ushort_as_bfloat16(H);
    m[o] = __ushort_as_bfloat16(M);
    l[o] = __ushort_as_bfloat16(L);
}

// in [K,N] fp32 -> out [N,K] bf16 2-way
__global__ __launch_bounds__(256) void transpose_split2_kernel(
    const float* __restrict__ in, __nv_bfloat16* __restrict__ h,
    __nv_bfloat16* __restrict__ l, int K, int N)
{
    int idx = blockIdx.x * 256 + threadIdx.x;
    if (idx >= K * N) return;
    int k = idx / N, n = idx - k * N;
    unsigned short H, L;
    split2v(in[idx], H, L);
    size_t o = (size_t)n * K + k;
    h[o] = __ushort_as_bfloat16(H);
    l[o] = __ushort_as_bfloat16(L);
}

__global__ void concat_bias_kernel(const float* __restrict__ a,
                                   const float* __restrict__ b,
                                   const float* __restrict__ c,
                                   float* __restrict__ o)
{
    int t = threadIdx.x;
    if (t < HDV) { o[t] = a[t]; o[HDV + t] = b[t]; o[2 * HDV + t] = c[t]; }
}

// ---------------------------------------------------------------------------
// HMMA GEMM, NSPLIT-way bf16 split operands (K-major A[M,K], B[N,K]).
// Precision strategy: each K=64 chunk's MMAs go into a FRESH (zeroed)
// accumulator (small-magnitude C -> tiny per-MMA rounding, smallest products
// first), then one fp32 RN add per chunk merges into the persistent master.
// This kills the quasi-linear MMA-chain rounding bias seen in R3/R4.
// CTA 128x128, BK=64, 256 threads (4x2 warps, warp tile 32x64).
// ---------------------------------------------------------------------------
#define TILE_B   16384                   // 128 rows x 128 bytes

template <int NSPLIT>
__global__ __launch_bounds__(256) void mma_gemm(
    const __nv_bfloat16* __restrict__ A0, const __nv_bfloat16* __restrict__ A1,
    const __nv_bfloat16* __restrict__ A2,
    const __nv_bfloat16* __restrict__ B0, const __nv_bfloat16* __restrict__ B1,
    const __nv_bfloat16* __restrict__ B2,
    const float* __restrict__ bias, float* __restrict__ O,
    int N, int K)
{
    constexpr int NT    = 2 * NSPLIT;
    constexpr int STAGE = NT * TILE_B;
    constexpr int NPROD = (NSPLIT == 3) ? 6 : 3;

    extern __shared__ char smem[];
    const uint32_t sbase = smem_to_u32(smem);
    const int tid = threadIdx.x;
    const int lane = tid & 31, wid = tid >> 5;
    const int warp_m = wid & 3;
    const int warp_n = wid >> 2;
    const int m0 = blockIdx.x * 128, n0 = blockIdx.y * 128;
    const int NC = K >> 6;

    const __nv_bfloat16* src[NT];
    src[0] = A0 + (size_t)m0 * K;
    src[1] = A1 + (size_t)m0 * K;
    if (NSPLIT == 3) src[2] = A2 + (size_t)m0 * K;
    src[NSPLIT + 0] = B0 + (size_t)n0 * K;
    src[NSPLIT + 1] = B1 + (size_t)n0 * K;
    if (NSPLIT == 3) src[NSPLIT + 2] = B2 + (size_t)n0 * K;

    const int lrow = tid >> 1;
    const int lhalf = tid & 1;

    float master[2][8][4];
#pragma unroll
    for (int a = 0; a < 2; a++)
#pragma unroll
        for (int b = 0; b < 8; b++)
#pragma unroll
            for (int c = 0; c < 4; c++) master[a][b][c] = 0.0f;

    auto load_stage = [&](int buf, int chunk) {
        const int kc = chunk << 6;
        const uint32_t sb = sbase + buf * STAGE;
#pragma unroll
        for (int t = 0; t < NT; t++) {
            const char* g = (const char*)(src[t] + (size_t)lrow * K + kc) + lhalf * 64;
            const uint32_t tb = sb + t * TILE_B;
#pragma unroll
            for (int i = 0; i < 4; i++) {
                uint32_t off = (uint32_t)(lrow * 128 + lhalf * 64 + i * 16);
                CP_ASYNC_CG(tb + SMEM_SWIZZLE_128B(off), g + i * 16);
            }
        }
    };

    load_stage(0, 0);
    CP_COMMIT();

    // product schedule, smallest magnitude FIRST (chunk acc grows last)
    // 3-split: mm(2^-18), lh, hl(2^-18), mh, hm(2^-9), hh(1)
    const int pa3[6] = {1, 2, 0, 1, 0, 0};
    const int pb3[6] = {1, 0, 2, 0, 1, 0};
    // 2-split: lh, hl(2^-9), hh(1)
    const int pa2[3] = {1, 0, 0};
    const int pb2[3] = {0, 1, 0};

    for (int c = 0; c < NC; c++) {
        const int s = c & 1;
        if (c + 1 < NC) { load_stage(s ^ 1, c + 1); CP_COMMIT(); CP_WAIT_1(); }
        else            { CP_WAIT_0(); }
        __syncthreads();

        // fresh per-chunk accumulator
        float chunk[2][8][4];
#pragma unroll
        for (int a = 0; a < 2; a++)
#pragma unroll
            for (int b = 0; b < 8; b++)
#pragma unroll
                for (int cc = 0; cc < 4; cc++) chunk[a][b][cc] = 0.0f;

        const uint32_t base = sbase + s * STAGE;
#pragma unroll
        for (int kk = 0; kk < 4; kk++) {
            uint32_t av[NSPLIT][2][4];
#pragma unroll
            for (int mt = 0; mt < 2; mt++) {
                int row = warp_m * 32 + mt * 16 + (lane & 15);
                int col = kk * 32 + ((lane >> 4) << 4);
                uint32_t off = SMEM_SWIZZLE_128B((uint32_t)(row * 128 + col));
#pragma unroll
                for (int t = 0; t < NSPLIT; t++)
                    ldsm_x4(av[t][mt], base + t * TILE_B + off);
            }
#pragma unroll
            for (int p = 0; p < 4; p++) {
                uint32_t bv[NSPLIT][2][2];
                int row = warp_n * 64 + p * 16 + (lane & 7) + (((lane >> 4) & 1) << 3);
                int col = kk * 32 + (((lane >> 3) & 1) << 4);
                uint32_t off = SMEM_SWIZZLE_128B((uint32_t)(row * 128 + col));
#pragma unroll
                for (int t = 0; t < NSPLIT; t++) {
                    uint32_t r[4];
                    ldsm_x4(r, base + (NSPLIT + t) * TILE_B + off);
                    bv[t][0][0] = r[0]; bv[t][0][1] = r[1];
                    bv[t][1][0] = r[2]; bv[t][1][1] = r[3];
                }
#pragma unroll
                for (int pr = 0; pr < NPROD; pr++) {
                    const int ia = (NSPLIT == 3) ? pa3[pr] : pa2[pr];
                    const int ib = (NSPLIT == 3) ? pb3[pr] : pb2[pr];
#pragma unroll
                    for (int mt = 0; mt < 2; mt++)
#pragma unroll
                        for (int n2 = 0; n2 < 2; n2++)
                            mma_bf16(chunk[mt][2 * p + n2], av[ia][mt],
                                     bv[ib][n2][0], bv[ib][n2][1]);
                }
            }
        }

        // single RN merge per chunk
#pragma unroll
        for (int a = 0; a < 2; a++)
#pragma unroll
            for (int b = 0; b < 8; b++)
#pragma unroll
                for (int cc = 0; cc < 4; cc++) master[a][b][cc] += chunk[a][b][cc];

        __syncthreads();
    }

    // ---- epilogue ----
    float2 bcol[8];
#pragma unroll
    for (int nt = 0; nt < 8; nt++) {
        int cbase = n0 + warp_n * 64 + nt * 8 + (lane & 3) * 2;
        bcol[nt].x = __ldg(bias + cbase);
        bcol[nt].y = __ldg(bias + cbase + 1);
    }
#pragma unroll
    for (int mt = 0; mt < 2; mt++) {
        int r0 = m0 + warp_m * 32 + mt * 16 + (lane >> 2);
#pragma unroll
        for (int nt = 0; nt < 8; nt++) {
            int cbase = n0 + warp_n * 64 + nt * 8 + (lane & 3) * 2;
            float2 v0 = { master[mt][nt][0] + bcol[nt].x, master[mt][nt][1] + bcol[nt].y };
            float2 v1 = { master[mt][nt][2] + bcol[nt].x, master[mt][nt][3] + bcol[nt].y };
            *reinterpret_cast<float2*>(O + (size_t)r0 * N + cbase) = v0;
            *reinterpret_cast<float2*>(O + (size_t)(r0 + 8) * N + cbase) = v1;
        }
    }
}

// ---------------------------------------------------------------------------
// Delta-rule scan: 1024 independent row-chains (B*HD), one warp per row.
// ---------------------------------------------------------------------------
__global__ __launch_bounds__(256) void titan_scan(
    const float* __restrict__ qkv, const float* __restrict__ state,
    const float* __restrict__ lr_ptr,
    float* __restrict__ ys, float* __restrict__ wfin)
{
    const int warp = threadIdx.x >> 5;
    const int lane = threadIdx.x & 31;
    const int gid  = blockIdx.x * 8 + warp;
    const int b    = gid >> 7;
    const int i    = gid & 127;

    const float lr = *lr_ptr;

    const float* qb = qkv + (size_t)b * SS * NQKV + lane * 4;
    const float* kb = qb + HDV;
    const float* vb = qkv + (size_t)b * SS * NQKV + 2 * HDV + i;
    float*       yb = ys + (size_t)b * SS * HDV + i;

    float4 w4 = *reinterpret_cast<const float4*>(
        state + ((size_t)b * HDV + i) * HDV + lane * 4);

    float4 qc = *reinterpret_cast<const float4*>(qb);
    float4 kc = *reinterpret_cast<const float4*>(kb);
    float  vc = *vb;

    for (int s = 0; s < SS; s++) {
        float4 qn = qc, kn = kc;
        float  vn = vc;
        if (s + 1 < SS) {
            qn = *reinterpret_cast<const float4*>(qb + (size_t)(s + 1) * NQKV);
            kn = *reinterpret_cast<const float4*>(kb + (size_t)(s + 1) * NQKV);
            vn = vb[(size_t)(s + 1) * NQKV];
        }

        float dq = w4.x * qc.x + w4.y * qc.y + w4.z * qc.z + w4.w * qc.w;
        float dk = w4.x * kc.x + w4.y * kc.y + w4.z * kc.z + w4.w * kc.w;
#pragma unroll
        for (int o = 16; o > 0; o >>= 1) {
            dq += __shfl_xor_sync(0xffffffffu, dq, o);
            dk += __shfl_xor_sync(0xffffffffu, dk, o);
        }

        if (lane == 0) yb[(size_t)s * HDV] = dq;

        float e = lr * (dk - vc);
        w4.x = fmaf(-e, kc.x, w4.x);
        w4.y = fmaf(-e, kc.y, w4.y);
        w4.z = fmaf(-e, kc.z, w4.z);
        w4.w = fmaf(-e, kc.w, w4.w);

        qc = qn; kc = kn; vc = vn;
    }

    *reinterpret_cast<float4*>(wfin + ((size_t)b * HDV + i) * HDV + lane * 4) = w4;
}

// ---------------------------------------------------------------------------
// Launch
// ---------------------------------------------------------------------------
extern "C" void kernel_launch(void* const* d_in, const int* in_sizes, int n_in,
                              void* d_out, int out_size)
{
    const float* x     = (const float*)d_in[0];
    const float* state = (const float*)d_in[1];
    const float* Wq    = (const float*)d_in[2];
    const float* bq    = (const float*)d_in[3];
    const float* Wk    = (const float*)d_in[4];
    const float* bk    = (const float*)d_in[5];
    const float* Wv    = (const float*)d_in[6];
    const float* bv    = (const float*)d_in[7];
    const float* Wo    = (const float*)d_in[8];
    const float* bo    = (const float*)d_in[9];
    const float* lr    = (const float*)d_in[10];
    float* out = (float*)d_out;

    __nv_bfloat16 *xh, *xm, *xl, *yh, *yl;
    __nv_bfloat16 *wqkvh, *wqkvm, *wqkvl, *woh, *wol;
    float *bqkv, *gqkv, *gy, *gws;
    cudaGetSymbolAddress((void**)&xh, g_xh);
    cudaGetSymbolAddress((void**)&xm, g_xm);
    cudaGetSymbolAddress((void**)&xl, g_xl);
    cudaGetSymbolAddress((void**)&yh, g_yh);
    cudaGetSymbolAddress((void**)&yl, g_yl);
    cudaGetSymbolAddress((void**)&wqkvh, g_wqkvh);
    cudaGetSymbolAddress((void**)&wqkvm, g_wqkvm);
    cudaGetSymbolAddress((void**)&wqkvl, g_wqkvl);
    cudaGetSymbolAddress((void**)&woh, g_woh);
    cudaGetSymbolAddress((void**)&wol, g_wol);
    cudaGetSymbolAddress((void**)&bqkv, g_bqkv);
    cudaGetSymbolAddress((void**)&gqkv, g_qkv);
    cudaGetSymbolAddress((void**)&gy, g_y);
    cudaGetSymbolAddress((void**)&gws, g_wfin_scratch);

    const size_t out_elems  = (size_t)BB * SS * DIMV;
    const size_t wfin_elems = (size_t)BB * HDV * HDV;
    float* wfin = ((size_t)out_size >= out_elems + wfin_elems)
                      ? (out + out_elems) : gws;

    const int SMEM3 = 2 * 6 * TILE_B;   // 196608
    const int SMEM2 = 2 * 4 * TILE_B;   // 131072
    cudaFuncSetAttribute(mma_gemm<3>, cudaFuncAttributeMaxDynamicSharedMemorySize, SMEM3);
    cudaFuncSetAttribute(mma_gemm<2>, cudaFuncAttributeMaxDynamicSharedMemorySize, SMEM2);

    // 1) prep: 3-way split x; 3-way transpose-split QKV weights; 2-way Wo
    {
        int n4 = MTOK * DIMV / 4;
        split3_kernel<<<(n4 + 255) / 256, 256>>>(x, xh, xm, xl, n4);
        int kn = DIMV * HDV;
        transpose_split3_kernel<<<(kn + 255) / 256, 256>>>(
            Wq, wqkvh + 0 * HDV * DIMV, wqkvm + 0 * HDV * DIMV, wqkvl + 0 * HDV * DIMV, DIMV, HDV);
        transpose_split3_kernel<<<(kn + 255) / 256, 256>>>(
            Wk, wqkvh + 1 * HDV * DIMV, wqkvm + 1 * HDV * DIMV, wqkvl + 1 * HDV * DIMV, DIMV, HDV);
        transpose_split3_kernel<<<(kn + 255) / 256, 256>>>(
            Wv, wqkvh + 2 * HDV * DIMV, wqkvm + 2 * HDV * DIMV, wqkvl + 2 * HDV * DIMV, DIMV, HDV);
        transpose_split2_kernel<<<(kn + 255) / 256, 256>>>(Wo, woh, wol, HDV, DIMV);
        concat_bias_kernel<<<1, 128>>>(bq, bk, bv, bqkv);
    }

    // 2) fused QKV projection (fp32-grade): [16384,2048] @ [2048,384]
    mma_gemm<3><<<dim3(MTOK / 128, NQKV / 128), 256, SMEM3>>>(
        xh, xm, xl, wqkvh, wqkvm, wqkvl, bqkv, gqkv, NQKV, DIMV);

    // 3) delta-rule scan
    titan_scan<<<128, 256>>>(gqkv, state, lr, gy, wfin);

    // 4) 2-way split y; output projection [16384,128] @ [128,2048]
    {
        int n4 = MTOK * HDV / 4;
        split2_kernel<<<(n4 + 255) / 256, 256>>>(gy, yh, yl, n4);
    }
    mma_gemm<2><<<dim3(MTOK / 128, DIMV / 128), 256, SMEM2>>>(
        yh, yl, nullptr, woh, wol, nullptr, bo, out, DIMV, HDV);
}

// round 7
// speedup vs baseline: 1.6657x; 1.1282x over previous
#include <cuda_runtime.h>
#include <cuda_fp16.h>
#include <cuda_bf16.h>
#include <cstdint>

#define BB   8
#define SS   2048
#define DIMV 2048
#define HDV  128
#define MTOK (BB*SS)        // 16384 tokens
#define NQKV 384            // q|k|v concat width
#define SPLIT_SCALE 2048.0f
#define INV_SPLIT   4.8828125e-4f   // 1/2048

// ---------------------------------------------------------------------------
// Scratch (device globals; no allocation allowed)
// ---------------------------------------------------------------------------
__device__ __half g_xh[MTOK * DIMV];
__device__ __half g_xl[MTOK * DIMV];
__device__ __half g_wqkvh[NQKV * DIMV];   // [384][2048] K-major
__device__ __half g_wqkvl[NQKV * DIMV];
__device__ __nv_bfloat16 g_woh[DIMV * HDV];  // [2048][128] K-major (bf16: range)
__device__ __nv_bfloat16 g_wol[DIMV * HDV];
__device__ float g_bqkv[NQKV];
__device__ float g_qkv[MTOK * NQKV];      // [token][384] = q|k|v
__device__ float g_y[MTOK * HDV];
__device__ __nv_bfloat16 g_yh[MTOK * HDV], g_yl[MTOK * HDV];  // bf16: y unbounded
__device__ float g_wfin_scratch[BB * HDV * HDV];

// ---------------------------------------------------------------------------
// Helpers
// ---------------------------------------------------------------------------
__device__ __forceinline__ uint32_t smem_to_u32(const void* p) {
    uint32_t a;
    asm("{ .reg .u64 t; cvta.to.shared.u64 t, %1; cvt.u32.u64 %0, t; }"
        : "=r"(a) : "l"(p));
    return a;
}

#define SMEM_SWIZZLE_128B(off) ((off) ^ (((off) >> 3) & 0x70))

#define CP_ASYNC_CG(dst, src) \
    asm volatile("cp.async.cg.shared.global [%0], [%1], 16;" \
        :: "r"(dst), "l"(src) : "memory")
#define CP_COMMIT() asm volatile("cp.async.commit_group;" ::: "memory")
#define CP_WAIT_1() asm volatile("cp.async.wait_group 1;" ::: "memory")
#define CP_WAIT_0() asm volatile("cp.async.wait_group 0;" ::: "memory")

__device__ __forceinline__ void ldsm_x4(uint32_t (&r)[4], uint32_t addr) {
    asm volatile("ldmatrix.sync.aligned.m8n8.x4.shared.b16 {%0,%1,%2,%3}, [%4];"
        : "=r"(r[0]), "=r"(r[1]), "=r"(r[2]), "=r"(r[3]) : "r"(addr));
}

template <bool BF16>
__device__ __forceinline__ void mma_16(float (&c)[4], const uint32_t (&a)[4],
                                       const uint32_t b0, const uint32_t b1) {
    if (BF16)
        asm volatile("mma.sync.aligned.m16n8k16.row.col.f32.bf16.bf16.f32 "
            "{%0,%1,%2,%3}, {%4,%5,%6,%7}, {%8,%9}, {%0,%1,%2,%3};"
            : "+f"(c[0]), "+f"(c[1]), "+f"(c[2]), "+f"(c[3])
            : "r"(a[0]), "r"(a[1]), "r"(a[2]), "r"(a[3]), "r"(b0), "r"(b1));
    else
        asm volatile("mma.sync.aligned.m16n8k16.row.col.f32.f16.f16.f32 "
            "{%0,%1,%2,%3}, {%4,%5,%6,%7}, {%8,%9}, {%0,%1,%2,%3};"
            : "+f"(c[0]), "+f"(c[1]), "+f"(c[2]), "+f"(c[3])
            : "r"(a[0]), "r"(a[1]), "r"(a[2]), "r"(a[3]), "r"(b0), "r"(b1));
}

// ---------------------------------------------------------------------------
// splits
// ---------------------------------------------------------------------------
// fp16 scaled: x ~= h + l/2048 (bounded inputs only!)
__device__ __forceinline__ void split2f(float x, unsigned short& h, unsigned short& l) {
    __half hh = __float2half_rn(x);
    float r = (x - __half2float(hh)) * SPLIT_SCALE;
    h = __half_as_ushort(hh);
    l = __half_as_ushort(__float2half_rn(r));
}
// bf16 plain: x ~= h + l (full fp32 range)
__device__ __forceinline__ void split2b(float x, unsigned short& h, unsigned short& l) {
    __nv_bfloat16 hh = __float2bfloat16(x);
    float r = x - __bfloat162float(hh);
    h = __bfloat16_as_ushort(hh);
    l = __bfloat16_as_ushort(__float2bfloat16(r));
}

__global__ __launch_bounds__(256) void split2f_kernel(
    const float* __restrict__ in, __half* __restrict__ h,
    __half* __restrict__ l, int n4)
{
    int i = blockIdx.x * 256 + threadIdx.x;
    if (i >= n4) return;
    float4 x = reinterpret_cast<const float4*>(in)[i];
    ushort4 H, L;
    split2f(x.x, H.x, L.x); split2f(x.y, H.y, L.y);
    split2f(x.z, H.z, L.z); split2f(x.w, H.w, L.w);
    reinterpret_cast<ushort4*>(h)[i] = H;
    reinterpret_cast<ushort4*>(l)[i] = L;
}

__global__ __launch_bounds__(256) void split2b_kernel(
    const float* __restrict__ in, __nv_bfloat16* __restrict__ h,
    __nv_bfloat16* __restrict__ l, int n4)
{
    int i = blockIdx.x * 256 + threadIdx.x;
    if (i >= n4) return;
    float4 x = reinterpret_cast<const float4*>(in)[i];
    ushort4 H, L;
    split2b(x.x, H.x, L.x); split2b(x.y, H.y, L.y);
    split2b(x.z, H.z, L.z); split2b(x.w, H.w, L.w);
    reinterpret_cast<ushort4*>(h)[i] = H;
    reinterpret_cast<ushort4*>(l)[i] = L;
}

// in [K,N] fp32 -> out [N,K] fp16 scaled split
__global__ __launch_bounds__(256) void transpose_split2f_kernel(
    const float* __restrict__ in, __half* __restrict__ h,
    __half* __restrict__ l, int K, int N)
{
    int idx = blockIdx.x * 256 + threadIdx.x;
    if (idx >= K * N) return;
    int k = idx / N, n = idx - k * N;
    unsigned short H, L;
    split2f(in[idx], H, L);
    size_t o = (size_t)n * K + k;
    h[o] = __ushort_as_half(H);
    l[o] = __ushort_as_half(L);
}

// in [K,N] fp32 -> out [N,K] bf16 split
__global__ __launch_bounds__(256) void transpose_split2b_kernel(
    const float* __restrict__ in, __nv_bfloat16* __restrict__ h,
    __nv_bfloat16* __restrict__ l, int K, int N)
{
    int idx = blockIdx.x * 256 + threadIdx.x;
    if (idx >= K * N) return;
    int k = idx / N, n = idx - k * N;
    unsigned short H, L;
    split2b(in[idx], H, L);
    size_t o = (size_t)n * K + k;
    h[o] = __ushort_as_bfloat16(H);
    l[o] = __ushort_as_bfloat16(L);
}

__global__ void concat_bias_kernel(const float* __restrict__ a,
                                   const float* __restrict__ b,
                                   const float* __restrict__ c,
                                   float* __restrict__ o)
{
    int t = threadIdx.x;
    if (t < HDV) { o[t] = a[t]; o[HDV + t] = b[t]; o[2 * HDV + t] = c[t]; }
}

// ---------------------------------------------------------------------------
// HMMA GEMM, 2-way split operands (K-major A[M,K], B[N,K]).
// BF16=false: fp16 scaled split (l' = l*2048), mixed-pass merged with 1/2048.
// BF16=true : bf16 plain split, mixed-pass merged with 1.0 (range-safe).
// Per K=64 chunk, two passes into a FRESH chunk accumulator:
//   pass A: h*l' + l'*h  -> master += chunk * mergeScale
//   pass B: h*h          -> master += chunk
// CTA 128x128, BK=64, 256 threads (4x2 warps, warp tile 32x64).
// ---------------------------------------------------------------------------
#define TILE_B   16384                   // 128 rows x 128 bytes
#define STAGE_B  (4 * TILE_B)            // Ah Al Bh Bl
#define SMEM_GEMM (2 * STAGE_B)          // 131072

template <bool BF16>
__global__ __launch_bounds__(256) void mma_gemm(
    const void* __restrict__ A0v, const void* __restrict__ A1v,
    const void* __restrict__ B0v, const void* __restrict__ B1v,
    const float* __restrict__ bias, float* __restrict__ O,
    int N, int K)
{
    const float mergeScale = BF16 ? 1.0f : INV_SPLIT;
    extern __shared__ char smem[];
    const uint32_t sbase = smem_to_u32(smem);
    const int tid = threadIdx.x;
    const int lane = tid & 31, wid = tid >> 5;
    const int warp_m = wid & 3;
    const int warp_n = wid >> 2;
    const int m0 = blockIdx.x * 128, n0 = blockIdx.y * 128;
    const int NC = K >> 6;

    const uint16_t* src[4] = {
        (const uint16_t*)A0v + (size_t)m0 * K, (const uint16_t*)A1v + (size_t)m0 * K,
        (const uint16_t*)B0v + (size_t)n0 * K, (const uint16_t*)B1v + (size_t)n0 * K };

    const int lrow = tid >> 1;
    const int lhalf = tid & 1;

    float master[2][8][4];
#pragma unroll
    for (int a = 0; a < 2; a++)
#pragma unroll
        for (int b = 0; b < 8; b++)
#pragma unroll
            for (int c = 0; c < 4; c++) master[a][b][c] = 0.0f;

    auto load_stage = [&](int buf, int chunk) {
        const int kc = chunk << 6;
        const uint32_t sb = sbase + buf * STAGE_B;
#pragma unroll
        for (int t = 0; t < 4; t++) {
            const char* g = (const char*)(src[t] + (size_t)lrow * K + kc) + lhalf * 64;
            const uint32_t tb = sb + t * TILE_B;
#pragma unroll
            for (int i = 0; i < 4; i++) {
                uint32_t off = (uint32_t)(lrow * 128 + lhalf * 64 + i * 16);
                CP_ASYNC_CG(tb + SMEM_SWIZZLE_128B(off), g + i * 16);
            }
        }
    };

    load_stage(0, 0);
    CP_COMMIT();

    float chunk[2][8][4];

    for (int c = 0; c < NC; c++) {
        const int s = c & 1;
        if (c + 1 < NC) { load_stage(s ^ 1, c + 1); CP_COMMIT(); CP_WAIT_1(); }
        else            { CP_WAIT_0(); }
        __syncthreads();

        const uint32_t base = sbase + s * STAGE_B;

        // ---- pass A: mixed products (h*l + l*h) ----
#pragma unroll
        for (int a = 0; a < 2; a++)
#pragma unroll
            for (int b = 0; b < 8; b++)
#pragma unroll
                for (int cc = 0; cc < 4; cc++) chunk[a][b][cc] = 0.0f;

#pragma unroll
        for (int kk = 0; kk < 4; kk++) {
            uint32_t ah[2][4], al[2][4];
#pragma unroll
            for (int mt = 0; mt < 2; mt++) {
                int row = warp_m * 32 + mt * 16 + (lane & 15);
                int col = kk * 32 + ((lane >> 4) << 4);
                uint32_t off = SMEM_SWIZZLE_128B((uint32_t)(row * 128 + col));
                ldsm_x4(ah[mt], base + off);
                ldsm_x4(al[mt], base + TILE_B + off);
            }
#pragma unroll
            for (int p = 0; p < 4; p++) {
                int row = warp_n * 64 + p * 16 + (lane & 7) + (((lane >> 4) & 1) << 3);
                int col = kk * 32 + (((lane >> 3) & 1) << 4);
                uint32_t off = SMEM_SWIZZLE_128B((uint32_t)(row * 128 + col));
                uint32_t bh[4], bl[4];
                ldsm_x4(bh, base + 2 * TILE_B + off);
                ldsm_x4(bl, base + 3 * TILE_B + off);
#pragma unroll
                for (int mt = 0; mt < 2; mt++)
#pragma unroll
                    for (int n2 = 0; n2 < 2; n2++) {
                        mma_16<BF16>(chunk[mt][2 * p + n2], ah[mt], bl[2 * n2], bl[2 * n2 + 1]);
                        mma_16<BF16>(chunk[mt][2 * p + n2], al[mt], bh[2 * n2], bh[2 * n2 + 1]);
                    }
            }
        }
#pragma unroll
        for (int a = 0; a < 2; a++)
#pragma unroll
            for (int b = 0; b < 8; b++)
#pragma unroll
                for (int cc = 0; cc < 4; cc++)
                    master[a][b][cc] = fmaf(chunk[a][b][cc], mergeScale, master[a][b][cc]);

        // ---- pass B: h*h ----
#pragma unroll
        for (int a = 0; a < 2; a++)
#pragma unroll
            for (int b = 0; b < 8; b++)
#pragma unroll
                for (int cc = 0; cc < 4; cc++) chunk[a][b][cc] = 0.0f;

#pragma unroll
        for (int kk = 0; kk < 4; kk++) {
            uint32_t ah[2][4];
#pragma unroll
            for (int mt = 0; mt < 2; mt++) {
                int row = warp_m * 32 + mt * 16 + (lane & 15);
                int col = kk * 32 + ((lane >> 4) << 4);
                uint32_t off = SMEM_SWIZZLE_128B((uint32_t)(row * 128 + col));
                ldsm_x4(ah[mt], base + off);
            }
#pragma unroll
            for (int p = 0; p < 4; p++) {
                int row = warp_n * 64 + p * 16 + (lane & 7) + (((lane >> 4) & 1) << 3);
                int col = kk * 32 + (((lane >> 3) & 1) << 4);
                uint32_t off = SMEM_SWIZZLE_128B((uint32_t)(row * 128 + col));
                uint32_t bh[4];
                ldsm_x4(bh, base + 2 * TILE_B + off);
#pragma unroll
                for (int mt = 0; mt < 2; mt++)
#pragma unroll
                    for (int n2 = 0; n2 < 2; n2++)
                        mma_16<BF16>(chunk[mt][2 * p + n2], ah[mt], bh[2 * n2], bh[2 * n2 + 1]);
            }
        }
#pragma unroll
        for (int a = 0; a < 2; a++)
#pragma unroll
            for (int b = 0; b < 8; b++)
#pragma unroll
                for (int cc = 0; cc < 4; cc++) master[a][b][cc] += chunk[a][b][cc];

        __syncthreads();
    }

    // ---- epilogue ----
    float2 bcol[8];
#pragma unroll
    for (int nt = 0; nt < 8; nt++) {
        int cbase = n0 + warp_n * 64 + nt * 8 + (lane & 3) * 2;
        bcol[nt].x = __ldg(bias + cbase);
        bcol[nt].y = __ldg(bias + cbase + 1);
    }
#pragma unroll
    for (int mt = 0; mt < 2; mt++) {
        int r0 = m0 + warp_m * 32 + mt * 16 + (lane >> 2);
#pragma unroll
        for (int nt = 0; nt < 8; nt++) {
            int cbase = n0 + warp_n * 64 + nt * 8 + (lane & 3) * 2;
            float2 v0 = { master[mt][nt][0] + bcol[nt].x, master[mt][nt][1] + bcol[nt].y };
            float2 v1 = { master[mt][nt][2] + bcol[nt].x, master[mt][nt][3] + bcol[nt].y };
            *reinterpret_cast<float2*>(O + (size_t)r0 * N + cbase) = v0;
            *reinterpret_cast<float2*>(O + (size_t)(r0 + 8) * N + cbase) = v1;
        }
    }
}

// ---------------------------------------------------------------------------
// Delta-rule scan: 1024 independent row-chains (B*HD), one warp per row.
// ---------------------------------------------------------------------------
__global__ __launch_bounds__(256) void titan_scan(
    const float* __restrict__ qkv, const float* __restrict__ state,
    const float* __restrict__ lr_ptr,
    float* __restrict__ ys, float* __restrict__ wfin)
{
    const int warp = threadIdx.x >> 5;
    const int lane = threadIdx.x & 31;
    const int gid  = blockIdx.x * 8 + warp;
    const int b    = gid >> 7;
    const int i    = gid & 127;

    const float lr = *lr_ptr;

    const float* qb = qkv + (size_t)b * SS * NQKV + lane * 4;
    const float* kb = qb + HDV;
    const float* vb = qkv + (size_t)b * SS * NQKV + 2 * HDV + i;
    float*       yb = ys + (size_t)b * SS * HDV + i;

    float4 w4 = *reinterpret_cast<const float4*>(
        state + ((size_t)b * HDV + i) * HDV + lane * 4);

    float4 qc = *reinterpret_cast<const float4*>(qb);
    float4 kc = *reinterpret_cast<const float4*>(kb);
    float  vc = *vb;

    for (int s = 0; s < SS; s++) {
        float4 qn = qc, kn = kc;
        float  vn = vc;
        if (s + 1 < SS) {
            qn = *reinterpret_cast<const float4*>(qb + (size_t)(s + 1) * NQKV);
            kn = *reinterpret_cast<const float4*>(kb + (size_t)(s + 1) * NQKV);
            vn = vb[(size_t)(s + 1) * NQKV];
        }

        float dq = w4.x * qc.x + w4.y * qc.y + w4.z * qc.z + w4.w * qc.w;
        float dk = w4.x * kc.x + w4.y * kc.y + w4.z * kc.z + w4.w * kc.w;
#pragma unroll
        for (int o = 16; o > 0; o >>= 1) {
            dq += __shfl_xor_sync(0xffffffffu, dq, o);
            dk += __shfl_xor_sync(0xffffffffu, dk, o);
        }

        if (lane == 0) yb[(size_t)s * HDV] = dq;

        float e = lr * (dk - vc);
        w4.x = fmaf(-e, kc.x, w4.x);
        w4.y = fmaf(-e, kc.y, w4.y);
        w4.z = fmaf(-e, kc.z, w4.z);
        w4.w = fmaf(-e, kc.w, w4.w);

        qc = qn; kc = kn; vc = vn;
    }

    *reinterpret_cast<float4*>(wfin + ((size_t)b * HDV + i) * HDV + lane * 4) = w4;
}

// ---------------------------------------------------------------------------
// Launch
// ---------------------------------------------------------------------------
extern "C" void kernel_launch(void* const* d_in, const int* in_sizes, int n_in,
                              void* d_out, int out_size)
{
    const float* x     = (const float*)d_in[0];
    const float* state = (const float*)d_in[1];
    const float* Wq    = (const float*)d_in[2];
    const float* bq    = (const float*)d_in[3];
    const float* Wk    = (const float*)d_in[4];
    const float* bk    = (const float*)d_in[5];
    const float* Wv    = (const float*)d_in[6];
    const float* bv    = (const float*)d_in[7];
    const float* Wo    = (const float*)d_in[8];
    const float* bo    = (const float*)d_in[9];
    const float* lr    = (const float*)d_in[10];
    float* out = (float*)d_out;

    __half *xh, *xl, *wqkvh, *wqkvl;
    __nv_bfloat16 *yh, *yl, *woh, *wol;
    float *bqkv, *gqkv, *gy, *gws;
    cudaGetSymbolAddress((void**)&xh, g_xh);
    cudaGetSymbolAddress((void**)&xl, g_xl);
    cudaGetSymbolAddress((void**)&yh, g_yh);
    cudaGetSymbolAddress((void**)&yl, g_yl);
    cudaGetSymbolAddress((void**)&wqkvh, g_wqkvh);
    cudaGetSymbolAddress((void**)&wqkvl, g_wqkvl);
    cudaGetSymbolAddress((void**)&woh, g_woh);
    cudaGetSymbolAddress((void**)&wol, g_wol);
    cudaGetSymbolAddress((void**)&bqkv, g_bqkv);
    cudaGetSymbolAddress((void**)&gqkv, g_qkv);
    cudaGetSymbolAddress((void**)&gy, g_y);
    cudaGetSymbolAddress((void**)&gws, g_wfin_scratch);

    const size_t out_elems  = (size_t)BB * SS * DIMV;
    const size_t wfin_elems = (size_t)BB * HDV * HDV;
    float* wfin = ((size_t)out_size >= out_elems + wfin_elems)
                      ? (out + out_elems) : gws;

    cudaFuncSetAttribute(mma_gemm<false>, cudaFuncAttributeMaxDynamicSharedMemorySize, SMEM_GEMM);
    cudaFuncSetAttribute(mma_gemm<true>,  cudaFuncAttributeMaxDynamicSharedMemorySize, SMEM_GEMM);

    // 1) prep: fp16-split x (bounded); fp16-split QKV weights; bf16-split Wo
    {
        int n4 = MTOK * DIMV / 4;
        split2f_kernel<<<(n4 + 255) / 256, 256>>>(x, xh, xl, n4);
        int kn = DIMV * HDV;
        transpose_split2f_kernel<<<(kn + 255) / 256, 256>>>(
            Wq, wqkvh + 0 * HDV * DIMV, wqkvl + 0 * HDV * DIMV, DIMV, HDV);
        transpose_split2f_kernel<<<(kn + 255) / 256, 256>>>(
            Wk, wqkvh + 1 * HDV * DIMV, wqkvl + 1 * HDV * DIMV, DIMV, HDV);
        transpose_split2f_kernel<<<(kn + 255) / 256, 256>>>(
            Wv, wqkvh + 2 * HDV * DIMV, wqkvl + 2 * HDV * DIMV, DIMV, HDV);
        transpose_split2b_kernel<<<(kn + 255) / 256, 256>>>(Wo, woh, wol, HDV, DIMV);
        concat_bias_kernel<<<1, 128>>>(bq, bk, bv, bqkv);
    }

    // 2) fused QKV projection (fp16 scaled split): [16384,2048] @ [2048,384]
    mma_gemm<false><<<dim3(MTOK / 128, NQKV / 128), 256, SMEM_GEMM>>>(
        xh, xl, wqkvh, wqkvl, bqkv, gqkv, NQKV, DIMV);

    // 3) delta-rule scan
    titan_scan<<<128, 256>>>(gqkv, state, lr, gy, wfin);

    // 4) bf16-split y (unbounded range); output projection [16384,128] @ [128,2048]
    {
        int n4 = MTOK * HDV / 4;
        split2b_kernel<<<(n4 + 255) / 256, 256>>>(gy, yh, yl, n4);
    }
    mma_gemm<true><<<dim3(MTOK / 128, DIMV / 128), 256, SMEM_GEMM>>>(
        yh, yl, woh, wol, bo, out, DIMV, HDV);
}

// round 8
// speedup vs baseline: 2.8812x; 1.7297x over previous
#include <cuda_runtime.h>
#include <cuda_fp16.h>
#include <cuda_bf16.h>
#include <cstdint>

#define BB   8
#define SS   2048
#define DIMV 2048
#define HDV  128
#define MTOK (BB*SS)        // 16384 tokens
#define NQKV 384            // q|k|v concat width
#define SPLIT_SCALE 2048.0f
#define INV_SPLIT   4.8828125e-4f   // 1/2048
#define SCAN_CH 16                   // scan smem chunk (steps)

// ---------------------------------------------------------------------------
// Scratch (device globals; no allocation allowed)
// ---------------------------------------------------------------------------
__device__ __half g_xh[MTOK * DIMV];
__device__ __half g_xl[MTOK * DIMV];
__device__ __half g_wqkvh[NQKV * DIMV];   // [384][2048] K-major
__device__ __half g_wqkvl[NQKV * DIMV];
__device__ __nv_bfloat16 g_woh[DIMV * HDV];  // [2048][128] K-major (bf16: range)
__device__ __nv_bfloat16 g_wol[DIMV * HDV];
__device__ float g_bqkv[NQKV];
__device__ float g_qkv[MTOK * NQKV];      // [token][384] = q|k|v
__device__ float g_y[MTOK * HDV];
__device__ __nv_bfloat16 g_yh[MTOK * HDV], g_yl[MTOK * HDV];  // bf16: y unbounded
__device__ float g_wfin_scratch[BB * HDV * HDV];

// ---------------------------------------------------------------------------
// Helpers
// ---------------------------------------------------------------------------
__device__ __forceinline__ uint32_t smem_to_u32(const void* p) {
    uint32_t a;
    asm("{ .reg .u64 t; cvta.to.shared.u64 t, %1; cvt.u32.u64 %0, t; }"
        : "=r"(a) : "l"(p));
    return a;
}

#define SMEM_SWIZZLE_128B(off) ((off) ^ (((off) >> 3) & 0x70))

#define CP_ASYNC_CG(dst, src) \
    asm volatile("cp.async.cg.shared.global [%0], [%1], 16;" \
        :: "r"(dst), "l"(src) : "memory")
#define CP_COMMIT() asm volatile("cp.async.commit_group;" ::: "memory")
#define CP_WAIT_1() asm volatile("cp.async.wait_group 1;" ::: "memory")
#define CP_WAIT_0() asm volatile("cp.async.wait_group 0;" ::: "memory")

__device__ __forceinline__ void ldsm_x4(uint32_t (&r)[4], uint32_t addr) {
    asm volatile("ldmatrix.sync.aligned.m8n8.x4.shared.b16 {%0,%1,%2,%3}, [%4];"
        : "=r"(r[0]), "=r"(r[1]), "=r"(r[2]), "=r"(r[3]) : "r"(addr));
}

template <bool BF16>
__device__ __forceinline__ void mma_16(float (&c)[4], const uint32_t (&a)[4],
                                       const uint32_t b0, const uint32_t b1) {
    if (BF16)
        asm volatile("mma.sync.aligned.m16n8k16.row.col.f32.bf16.bf16.f32 "
            "{%0,%1,%2,%3}, {%4,%5,%6,%7}, {%8,%9}, {%0,%1,%2,%3};"
            : "+f"(c[0]), "+f"(c[1]), "+f"(c[2]), "+f"(c[3])
            : "r"(a[0]), "r"(a[1]), "r"(a[2]), "r"(a[3]), "r"(b0), "r"(b1));
    else
        asm volatile("mma.sync.aligned.m16n8k16.row.col.f32.f16.f16.f32 "
            "{%0,%1,%2,%3}, {%4,%5,%6,%7}, {%8,%9}, {%0,%1,%2,%3};"
            : "+f"(c[0]), "+f"(c[1]), "+f"(c[2]), "+f"(c[3])
            : "r"(a[0]), "r"(a[1]), "r"(a[2]), "r"(a[3]), "r"(b0), "r"(b1));
}

// ---------------------------------------------------------------------------
// splits
// ---------------------------------------------------------------------------
__device__ __forceinline__ void split2f(float x, unsigned short& h, unsigned short& l) {
    __half hh = __float2half_rn(x);
    float r = (x - __half2float(hh)) * SPLIT_SCALE;
    h = __half_as_ushort(hh);
    l = __half_as_ushort(__float2half_rn(r));
}
__device__ __forceinline__ void split2b(float x, unsigned short& h, unsigned short& l) {
    __nv_bfloat16 hh = __float2bfloat16(x);
    float r = x - __bfloat162float(hh);
    h = __bfloat16_as_ushort(hh);
    l = __bfloat16_as_ushort(__float2bfloat16(r));
}

__global__ __launch_bounds__(256) void split2f_kernel(
    const float* __restrict__ in, __half* __restrict__ h,
    __half* __restrict__ l, int n4)
{
    int i = blockIdx.x * 256 + threadIdx.x;
    if (i >= n4) return;
    float4 x = reinterpret_cast<const float4*>(in)[i];
    ushort4 H, L;
    split2f(x.x, H.x, L.x); split2f(x.y, H.y, L.y);
    split2f(x.z, H.z, L.z); split2f(x.w, H.w, L.w);
    reinterpret_cast<ushort4*>(h)[i] = H;
    reinterpret_cast<ushort4*>(l)[i] = L;
}

__global__ __launch_bounds__(256) void split2b_kernel(
    const float* __restrict__ in, __nv_bfloat16* __restrict__ h,
    __nv_bfloat16* __restrict__ l, int n4)
{
    int i = blockIdx.x * 256 + threadIdx.x;
    if (i >= n4) return;
    float4 x = reinterpret_cast<const float4*>(in)[i];
    ushort4 H, L;
    split2b(x.x, H.x, L.x); split2b(x.y, H.y, L.y);
    split2b(x.z, H.z, L.z); split2b(x.w, H.w, L.w);
    reinterpret_cast<ushort4*>(h)[i] = H;
    reinterpret_cast<ushort4*>(l)[i] = L;
}

__global__ __launch_bounds__(256) void transpose_split2f_kernel(
    const float* __restrict__ in, __half* __restrict__ h,
    __half* __restrict__ l, int K, int N)
{
    int idx = blockIdx.x * 256 + threadIdx.x;
    if (idx >= K * N) return;
    int k = idx / N, n = idx - k * N;
    unsigned short H, L;
    split2f(in[idx], H, L);
    size_t o = (size_t)n * K + k;
    h[o] = __ushort_as_half(H);
    l[o] = __ushort_as_half(L);
}

__global__ __launch_bounds__(256) void transpose_split2b_kernel(
    const float* __restrict__ in, __nv_bfloat16* __restrict__ h,
    __nv_bfloat16* __restrict__ l, int K, int N)
{
    int idx = blockIdx.x * 256 + threadIdx.x;
    if (idx >= K * N) return;
    int k = idx / N, n = idx - k * N;
    unsigned short H, L;
    split2b(in[idx], H, L);
    size_t o = (size_t)n * K + k;
    h[o] = __ushort_as_bfloat16(H);
    l[o] = __ushort_as_bfloat16(L);
}

__global__ void concat_bias_kernel(const float* __restrict__ a,
                                   const float* __restrict__ b,
                                   const float* __restrict__ c,
                                   float* __restrict__ o)
{
    int t = threadIdx.x;
    if (t < HDV) { o[t] = a[t]; o[HDV + t] = b[t]; o[2 * HDV + t] = c[t]; }
}

// ---------------------------------------------------------------------------
// HMMA GEMM, 2-way split operands (unchanged from R7)
// ---------------------------------------------------------------------------
#define TILE_B   16384
#define STAGE_B  (4 * TILE_B)
#define SMEM_GEMM (2 * STAGE_B)

template <bool BF16>
__global__ __launch_bounds__(256) void mma_gemm(
    const void* __restrict__ A0v, const void* __restrict__ A1v,
    const void* __restrict__ B0v, const void* __restrict__ B1v,
    const float* __restrict__ bias, float* __restrict__ O,
    int N, int K)
{
    const float mergeScale = BF16 ? 1.0f : INV_SPLIT;
    extern __shared__ char smem[];
    const uint32_t sbase = smem_to_u32(smem);
    const int tid = threadIdx.x;
    const int lane = tid & 31, wid = tid >> 5;
    const int warp_m = wid & 3;
    const int warp_n = wid >> 2;
    const int m0 = blockIdx.x * 128, n0 = blockIdx.y * 128;
    const int NC = K >> 6;

    const uint16_t* src[4] = {
        (const uint16_t*)A0v + (size_t)m0 * K, (const uint16_t*)A1v + (size_t)m0 * K,
        (const uint16_t*)B0v + (size_t)n0 * K, (const uint16_t*)B1v + (size_t)n0 * K };

    const int lrow = tid >> 1;
    const int lhalf = tid & 1;

    float master[2][8][4];
#pragma unroll
    for (int a = 0; a < 2; a++)
#pragma unroll
        for (int b = 0; b < 8; b++)
#pragma unroll
            for (int c = 0; c < 4; c++) master[a][b][c] = 0.0f;

    auto load_stage = [&](int buf, int chunk) {
        const int kc = chunk << 6;
        const uint32_t sb = sbase + buf * STAGE_B;
#pragma unroll
        for (int t = 0; t < 4; t++) {
            const char* g = (const char*)(src[t] + (size_t)lrow * K + kc) + lhalf * 64;
            const uint32_t tb = sb + t * TILE_B;
#pragma unroll
            for (int i = 0; i < 4; i++) {
                uint32_t off = (uint32_t)(lrow * 128 + lhalf * 64 + i * 16);
                CP_ASYNC_CG(tb + SMEM_SWIZZLE_128B(off), g + i * 16);
            }
        }
    };

    load_stage(0, 0);
    CP_COMMIT();

    float chunk[2][8][4];

    for (int c = 0; c < NC; c++) {
        const int s = c & 1;
        if (c + 1 < NC) { load_stage(s ^ 1, c + 1); CP_COMMIT(); CP_WAIT_1(); }
        else            { CP_WAIT_0(); }
        __syncthreads();

        const uint32_t base = sbase + s * STAGE_B;

        // ---- pass A: mixed products (h*l + l*h) ----
#pragma unroll
        for (int a = 0; a < 2; a++)
#pragma unroll
            for (int b = 0; b < 8; b++)
#pragma unroll
                for (int cc = 0; cc < 4; cc++) chunk[a][b][cc] = 0.0f;

#pragma unroll
        for (int kk = 0; kk < 4; kk++) {
            uint32_t ah[2][4], al[2][4];
#pragma unroll
            for (int mt = 0; mt < 2; mt++) {
                int row = warp_m * 32 + mt * 16 + (lane & 15);
                int col = kk * 32 + ((lane >> 4) << 4);
                uint32_t off = SMEM_SWIZZLE_128B((uint32_t)(row * 128 + col));
                ldsm_x4(ah[mt], base + off);
                ldsm_x4(al[mt], base + TILE_B + off);
            }
#pragma unroll
            for (int p = 0; p < 4; p++) {
                int row = warp_n * 64 + p * 16 + (lane & 7) + (((lane >> 4) & 1) << 3);
                int col = kk * 32 + (((lane >> 3) & 1) << 4);
                uint32_t off = SMEM_SWIZZLE_128B((uint32_t)(row * 128 + col));
                uint32_t bh[4], bl[4];
                ldsm_x4(bh, base + 2 * TILE_B + off);
                ldsm_x4(bl, base + 3 * TILE_B + off);
#pragma unroll
                for (int mt = 0; mt < 2; mt++)
#pragma unroll
                    for (int n2 = 0; n2 < 2; n2++) {
                        mma_16<BF16>(chunk[mt][2 * p + n2], ah[mt], bl[2 * n2], bl[2 * n2 + 1]);
                        mma_16<BF16>(chunk[mt][2 * p + n2], al[mt], bh[2 * n2], bh[2 * n2 + 1]);
                    }
            }
        }
#pragma unroll
        for (int a = 0; a < 2; a++)
#pragma unroll
            for (int b = 0; b < 8; b++)
#pragma unroll
                for (int cc = 0; cc < 4; cc++)
                    master[a][b][cc] = fmaf(chunk[a][b][cc], mergeScale, master[a][b][cc]);

        // ---- pass B: h*h ----
#pragma unroll
        for (int a = 0; a < 2; a++)
#pragma unroll
            for (int b = 0; b < 8; b++)
#pragma unroll
                for (int cc = 0; cc < 4; cc++) chunk[a][b][cc] = 0.0f;

#pragma unroll
        for (int kk = 0; kk < 4; kk++) {
            uint32_t ah[2][4];
#pragma unroll
            for (int mt = 0; mt < 2; mt++) {
                int row = warp_m * 32 + mt * 16 + (lane & 15);
                int col = kk * 32 + ((lane >> 4) << 4);
                uint32_t off = SMEM_SWIZZLE_128B((uint32_t)(row * 128 + col));
                ldsm_x4(ah[mt], base + off);
            }
#pragma unroll
            for (int p = 0; p < 4; p++) {
                int row = warp_n * 64 + p * 16 + (lane & 7) + (((lane >> 4) & 1) << 3);
                int col = kk * 32 + (((lane >> 3) & 1) << 4);
                uint32_t off = SMEM_SWIZZLE_128B((uint32_t)(row * 128 + col));
                uint32_t bh[4];
                ldsm_x4(bh, base + 2 * TILE_B + off);
#pragma unroll
                for (int mt = 0; mt < 2; mt++)
#pragma unroll
                    for (int n2 = 0; n2 < 2; n2++)
                        mma_16<BF16>(chunk[mt][2 * p + n2], ah[mt], bh[2 * n2], bh[2 * n2 + 1]);
            }
        }
#pragma unroll
        for (int a = 0; a < 2; a++)
#pragma unroll
            for (int b = 0; b < 8; b++)
#pragma unroll
                for (int cc = 0; cc < 4; cc++) master[a][b][cc] += chunk[a][b][cc];

        __syncthreads();
    }

    // ---- epilogue ----
    float2 bcol[8];
#pragma unroll
    for (int nt = 0; nt < 8; nt++) {
        int cbase = n0 + warp_n * 64 + nt * 8 + (lane & 3) * 2;
        bcol[nt].x = __ldg(bias + cbase);
        bcol[nt].y = __ldg(bias + cbase + 1);
    }
#pragma unroll
    for (int mt = 0; mt < 2; mt++) {
        int r0 = m0 + warp_m * 32 + mt * 16 + (lane >> 2);
#pragma unroll
        for (int nt = 0; nt < 8; nt++) {
            int cbase = n0 + warp_n * 64 + nt * 8 + (lane & 3) * 2;
            float2 v0 = { master[mt][nt][0] + bcol[nt].x, master[mt][nt][1] + bcol[nt].y };
            float2 v1 = { master[mt][nt][2] + bcol[nt].x, master[mt][nt][3] + bcol[nt].y };
            *reinterpret_cast<float2*>(O + (size_t)r0 * N + cbase) = v0;
            *reinterpret_cast<float2*>(O + (size_t)(r0 + 8) * N + cbase) = v1;
        }
    }
}

// ---------------------------------------------------------------------------
// Delta-rule scan v2: lookahead dots + smem staging.
//   dq_{s+1} = W_s.q_{s+1} - e_s*(k_s.q_{s+1});  dk_{s+1} = W_s.k_{s+1} - e_s*(k_s.k_{s+1})
// Four dots (a,b,c,d) reduced jointly; serial chain = a few scalar FMAs.
// Blocks are batch-coherent: blockIdx>>4 = batch, 8 warps = 8 W-rows.
// qkv rows staged per 16-step chunk (24KB contiguous) via cp.async, 2 stages.
// ---------------------------------------------------------------------------
#define SCAN_SMEM (2 * SCAN_CH * NQKV * 4)   // 49152 bytes

__global__ __launch_bounds__(256) void titan_scan(
    const float* __restrict__ qkv, const float* __restrict__ state,
    const float* __restrict__ lr_ptr,
    float* __restrict__ ys, float* __restrict__ wfin)
{
    extern __shared__ float sqkv[];          // [2][SCAN_CH][NQKV]
    const int tid  = threadIdx.x;
    const int warp = tid >> 5;
    const int lane = tid & 31;
    const int b    = blockIdx.x >> 4;
    const int i    = ((blockIdx.x & 15) << 3) + warp;

    const float lr = *lr_ptr;
    const float* base = qkv + (size_t)b * SS * NQKV;
    float* yb = ys + (size_t)b * SS * HDV + i;

    const uint32_t s0 = smem_to_u32(sqkv);
    auto stage = [&](int c) {
        if (c < SS / SCAN_CH) {
            const char* g = (const char*)(base + (size_t)c * SCAN_CH * NQKV);
            const uint32_t sb = s0 + (uint32_t)(c & 1) * (SCAN_CH * NQKV * 4);
#pragma unroll
            for (int it = 0; it < 6; it++) {
                int idx = tid + it * 256;
                CP_ASYNC_CG(sb + idx * 16, g + idx * 16);
            }
        }
    };
    stage(0); CP_COMMIT();
    stage(1); CP_COMMIT();

    float4 w4 = *reinterpret_cast<const float4*>(
        state + ((size_t)b * HDV + i) * HDV + lane * 4);

    // ---- prologue: step 0 directly from gmem ----
    float4 q0 = *reinterpret_cast<const float4*>(base + lane * 4);
    float4 kc = *reinterpret_cast<const float4*>(base + 128 + lane * 4);
    float  v_cur = __ldg(base + 256 + i);

    float dq0 = w4.x * q0.x + w4.y * q0.y + w4.z * q0.z + w4.w * q0.w;
    float dk_cur = w4.x * kc.x + w4.y * kc.y + w4.z * kc.z + w4.w * kc.w;
#pragma unroll
    for (int o = 16; o > 0; o >>= 1) {
        dq0    += __shfl_xor_sync(0xffffffffu, dq0, o);
        dk_cur += __shfl_xor_sync(0xffffffffu, dk_cur, o);
    }
    if (lane == 0) yb[0] = dq0;

    for (int c = 0; c < SS / SCAN_CH; c++) {
        CP_WAIT_1();
        __syncthreads();
        const float* sb = sqkv + (c & 1) * (SCAN_CH * NQKV);
        const int j0 = (c == 0) ? 1 : 0;
        for (int j = j0; j < SCAN_CH; j++) {
            const float* row = sb + j * NQKV;
            float4 q1 = *reinterpret_cast<const float4*>(row + lane * 4);
            float4 k1 = *reinterpret_cast<const float4*>(row + 128 + lane * 4);
            float  v1 = row[256 + i];

            float a  = w4.x * q1.x + w4.y * q1.y + w4.z * q1.z + w4.w * q1.w;
            float bb = w4.x * k1.x + w4.y * k1.y + w4.z * k1.z + w4.w * k1.w;
            float cc = kc.x * q1.x + kc.y * q1.y + kc.z * q1.z + kc.w * q1.w;
            float dd = kc.x * k1.x + kc.y * k1.y + kc.z * k1.z + kc.w * k1.w;
#pragma unroll
            for (int o = 16; o > 0; o >>= 1) {
                a  += __shfl_xor_sync(0xffffffffu, a,  o);
                bb += __shfl_xor_sync(0xffffffffu, bb, o);
                cc += __shfl_xor_sync(0xffffffffu, cc, o);
                dd += __shfl_xor_sync(0xffffffffu, dd, o);
            }

            float e = lr * (dk_cur - v_cur);
            w4.x = fmaf(-e, kc.x, w4.x);
            w4.y = fmaf(-e, kc.y, w4.y);
            w4.z = fmaf(-e, kc.z, w4.z);
            w4.w = fmaf(-e, kc.w, w4.w);

            float dqn = fmaf(-e, cc, a);
            dk_cur    = fmaf(-e, dd, bb);
            if (lane == 0) yb[(size_t)(c * SCAN_CH + j) * HDV] = dqn;

            v_cur = v1;
            kc = k1;
        }
        __syncthreads();
        stage(c + 2); CP_COMMIT();
    }

    // ---- final update for step SS-1 ----
    float e = lr * (dk_cur - v_cur);
    w4.x = fmaf(-e, kc.x, w4.x);
    w4.y = fmaf(-e, kc.y, w4.y);
    w4.z = fmaf(-e, kc.z, w4.z);
    w4.w = fmaf(-e, kc.w, w4.w);

    *reinterpret_cast<float4*>(wfin + ((size_t)b * HDV + i) * HDV + lane * 4) = w4;
}

// ---------------------------------------------------------------------------
// Launch
// ---------------------------------------------------------------------------
extern "C" void kernel_launch(void* const* d_in, const int* in_sizes, int n_in,
                              void* d_out, int out_size)
{
    const float* x     = (const float*)d_in[0];
    const float* state = (const float*)d_in[1];
    const float* Wq    = (const float*)d_in[2];
    const float* bq    = (const float*)d_in[3];
    const float* Wk    = (const float*)d_in[4];
    const float* bk    = (const float*)d_in[5];
    const float* Wv    = (const float*)d_in[6];
    const float* bv    = (const float*)d_in[7];
    const float* Wo    = (const float*)d_in[8];
    const float* bo    = (const float*)d_in[9];
    const float* lr    = (const float*)d_in[10];
    float* out = (float*)d_out;

    __half *xh, *xl, *wqkvh, *wqkvl;
    __nv_bfloat16 *yh, *yl, *woh, *wol;
    float *bqkv, *gqkv, *gy, *gws;
    cudaGetSymbolAddress((void**)&xh, g_xh);
    cudaGetSymbolAddress((void**)&xl, g_xl);
    cudaGetSymbolAddress((void**)&yh, g_yh);
    cudaGetSymbolAddress((void**)&yl, g_yl);
    cudaGetSymbolAddress((void**)&wqkvh, g_wqkvh);
    cudaGetSymbolAddress((void**)&wqkvl, g_wqkvl);
    cudaGetSymbolAddress((void**)&woh, g_woh);
    cudaGetSymbolAddress((void**)&wol, g_wol);
    cudaGetSymbolAddress((void**)&bqkv, g_bqkv);
    cudaGetSymbolAddress((void**)&gqkv, g_qkv);
    cudaGetSymbolAddress((void**)&gy, g_y);
    cudaGetSymbolAddress((void**)&gws, g_wfin_scratch);

    const size_t out_elems  = (size_t)BB * SS * DIMV;
    const size_t wfin_elems = (size_t)BB * HDV * HDV;
    float* wfin = ((size_t)out_size >= out_elems + wfin_elems)
                      ? (out + out_elems) : gws;

    cudaFuncSetAttribute(mma_gemm<false>, cudaFuncAttributeMaxDynamicSharedMemorySize, SMEM_GEMM);
    cudaFuncSetAttribute(mma_gemm<true>,  cudaFuncAttributeMaxDynamicSharedMemorySize, SMEM_GEMM);
    cudaFuncSetAttribute(titan_scan,      cudaFuncAttributeMaxDynamicSharedMemorySize, SCAN_SMEM);

    // 1) prep
    {
        int n4 = MTOK * DIMV / 4;
        split2f_kernel<<<(n4 + 255) / 256, 256>>>(x, xh, xl, n4);
        int kn = DIMV * HDV;
        transpose_split2f_kernel<<<(kn + 255) / 256, 256>>>(
            Wq, wqkvh + 0 * HDV * DIMV, wqkvl + 0 * HDV * DIMV, DIMV, HDV);
        transpose_split2f_kernel<<<(kn + 255) / 256, 256>>>(
            Wk, wqkvh + 1 * HDV * DIMV, wqkvl + 1 * HDV * DIMV, DIMV, HDV);
        transpose_split2f_kernel<<<(kn + 255) / 256, 256>>>(
            Wv, wqkvh + 2 * HDV * DIMV, wqkvl + 2 * HDV * DIMV, DIMV, HDV);
        transpose_split2b_kernel<<<(kn + 255) / 256, 256>>>(Wo, woh, wol, HDV, DIMV);
        concat_bias_kernel<<<1, 128>>>(bq, bk, bv, bqkv);
    }

    // 2) fused QKV projection (fp16 scaled split): [16384,2048] @ [2048,384]
    mma_gemm<false><<<dim3(MTOK / 128, NQKV / 128), 256, SMEM_GEMM>>>(
        xh, xl, wqkvh, wqkvl, bqkv, gqkv, NQKV, DIMV);

    // 3) delta-rule scan (lookahead + smem staging)
    titan_scan<<<128, 256, SCAN_SMEM>>>(gqkv, state, lr, gy, wfin);

    // 4) bf16-split y; output projection [16384,128] @ [128,2048]
    {
        int n4 = MTOK * HDV / 4;
        split2b_kernel<<<(n4 + 255) / 256, 256>>>(gy, yh, yl, n4);
    }
    mma_gemm<true><<<dim3(MTOK / 128, DIMV / 128), 256, SMEM_GEMM>>>(
        yh, yl, woh, wol, bo, out, DIMV, HDV);
}

// round 9
// speedup vs baseline: 3.5115x; 1.2188x over previous
#include <cuda_runtime.h>
#include <cuda_fp16.h>
#include <cuda_bf16.h>
#include <cstdint>

#define BB   8
#define SS   2048
#define DIMV 2048
#define HDV  128
#define MTOK (BB*SS)        // 16384 tokens
#define NQKV 384            // q|k|v concat width
#define SPLIT_SCALE 2048.0f
#define INV_SPLIT   4.8828125e-4f   // 1/2048
#define SCAN_CH 16                   // scan chunk (steps)
#define NCHUNK (SS / SCAN_CH)        // 128

// ---------------------------------------------------------------------------
// Scratch (device globals; no allocation allowed)
// ---------------------------------------------------------------------------
__device__ __half g_xh[MTOK * DIMV];
__device__ __half g_xl[MTOK * DIMV];
__device__ __half g_wqkvh[NQKV * DIMV];   // [384][2048] K-major
__device__ __half g_wqkvl[NQKV * DIMV];
__device__ __nv_bfloat16 g_woh[DIMV * HDV];  // [2048][128] K-major (bf16: range)
__device__ __nv_bfloat16 g_wol[DIMV * HDV];
__device__ float g_bqkv[NQKV];
__device__ float g_qkv[MTOK * NQKV];      // [token][384] = q|k|v
__device__ float g_y[MTOK * HDV];
__device__ __nv_bfloat16 g_yh[MTOK * HDV], g_yl[MTOK * HDV];
__device__ float g_wfin_scratch[BB * HDV * HDV];
__device__ float g_G[BB * NCHUNK * 512];  // per chunk: [256]=k.k, [256]=k.q

// ---------------------------------------------------------------------------
// Helpers
// ---------------------------------------------------------------------------
__device__ __forceinline__ uint32_t smem_to_u32(const void* p) {
    uint32_t a;
    asm("{ .reg .u64 t; cvta.to.shared.u64 t, %1; cvt.u32.u64 %0, t; }"
        : "=r"(a) : "l"(p));
    return a;
}

#define SMEM_SWIZZLE_128B(off) ((off) ^ (((off) >> 3) & 0x70))

#define CP_ASYNC_CG(dst, src) \
    asm volatile("cp.async.cg.shared.global [%0], [%1], 16;" \
        :: "r"(dst), "l"(src) : "memory")
#define CP_COMMIT() asm volatile("cp.async.commit_group;" ::: "memory")
#define CP_WAIT_1() asm volatile("cp.async.wait_group 1;" ::: "memory")
#define CP_WAIT_0() asm volatile("cp.async.wait_group 0;" ::: "memory")

__device__ __forceinline__ void ldsm_x4(uint32_t (&r)[4], uint32_t addr) {
    asm volatile("ldmatrix.sync.aligned.m8n8.x4.shared.b16 {%0,%1,%2,%3}, [%4];"
        : "=r"(r[0]), "=r"(r[1]), "=r"(r[2]), "=r"(r[3]) : "r"(addr));
}

template <bool BF16>
__device__ __forceinline__ void mma_16(float (&c)[4], const uint32_t (&a)[4],
                                       const uint32_t b0, const uint32_t b1) {
    if (BF16)
        asm volatile("mma.sync.aligned.m16n8k16.row.col.f32.bf16.bf16.f32 "
            "{%0,%1,%2,%3}, {%4,%5,%6,%7}, {%8,%9}, {%0,%1,%2,%3};"
            : "+f"(c[0]), "+f"(c[1]), "+f"(c[2]), "+f"(c[3])
            : "r"(a[0]), "r"(a[1]), "r"(a[2]), "r"(a[3]), "r"(b0), "r"(b1));
    else
        asm volatile("mma.sync.aligned.m16n8k16.row.col.f32.f16.f16.f32 "
            "{%0,%1,%2,%3}, {%4,%5,%6,%7}, {%8,%9}, {%0,%1,%2,%3};"
            : "+f"(c[0]), "+f"(c[1]), "+f"(c[2]), "+f"(c[3])
            : "r"(a[0]), "r"(a[1]), "r"(a[2]), "r"(a[3]), "r"(b0), "r"(b1));
}

// ---------------------------------------------------------------------------
// splits
// ---------------------------------------------------------------------------
__device__ __forceinline__ void split2f(float x, unsigned short& h, unsigned short& l) {
    __half hh = __float2half_rn(x);
    float r = (x - __half2float(hh)) * SPLIT_SCALE;
    h = __half_as_ushort(hh);
    l = __half_as_ushort(__float2half_rn(r));
}
__device__ __forceinline__ void split2b(float x, unsigned short& h, unsigned short& l) {
    __nv_bfloat16 hh = __float2bfloat16(x);
    float r = x - __bfloat162float(hh);
    h = __bfloat16_as_ushort(hh);
    l = __bfloat16_as_ushort(__float2bfloat16(r));
}

__global__ __launch_bounds__(256) void split2f_kernel(
    const float* __restrict__ in, __half* __restrict__ h,
    __half* __restrict__ l, int n4)
{
    int i = blockIdx.x * 256 + threadIdx.x;
    if (i >= n4) return;
    float4 x = reinterpret_cast<const float4*>(in)[i];
    ushort4 H, L;
    split2f(x.x, H.x, L.x); split2f(x.y, H.y, L.y);
    split2f(x.z, H.z, L.z); split2f(x.w, H.w, L.w);
    reinterpret_cast<ushort4*>(h)[i] = H;
    reinterpret_cast<ushort4*>(l)[i] = L;
}

__global__ __launch_bounds__(256) void split2b_kernel(
    const float* __restrict__ in, __nv_bfloat16* __restrict__ h,
    __nv_bfloat16* __restrict__ l, int n4)
{
    int i = blockIdx.x * 256 + threadIdx.x;
    if (i >= n4) return;
    float4 x = reinterpret_cast<const float4*>(in)[i];
    ushort4 H, L;
    split2b(x.x, H.x, L.x); split2b(x.y, H.y, L.y);
    split2b(x.z, H.z, L.z); split2b(x.w, H.w, L.w);
    reinterpret_cast<ushort4*>(h)[i] = H;
    reinterpret_cast<ushort4*>(l)[i] = L;
}

__global__ __launch_bounds__(256) void transpose_split2f_kernel(
    const float* __restrict__ in, __half* __restrict__ h,
    __half* __restrict__ l, int K, int N)
{
    int idx = blockIdx.x * 256 + threadIdx.x;
    if (idx >= K * N) return;
    int k = idx / N, n = idx - k * N;
    unsigned short H, L;
    split2f(in[idx], H, L);
    size_t o = (size_t)n * K + k;
    h[o] = __ushort_as_half(H);
    l[o] = __ushort_as_half(L);
}

__global__ __launch_bounds__(256) void transpose_split2b_kernel(
    const float* __restrict__ in, __nv_bfloat16* __restrict__ h,
    __nv_bfloat16* __restrict__ l, int K, int N)
{
    int idx = blockIdx.x * 256 + threadIdx.x;
    if (idx >= K * N) return;
    int k = idx / N, n = idx - k * N;
    unsigned short H, L;
    split2b(in[idx], H, L);
    size_t o = (size_t)n * K + k;
    h[o] = __ushort_as_bfloat16(H);
    l[o] = __ushort_as_bfloat16(L);
}

__global__ void concat_bias_kernel(const float* __restrict__ a,
                                   const float* __restrict__ b,
                                   const float* __restrict__ c,
                                   float* __restrict__ o)
{
    int t = threadIdx.x;
    if (t < HDV) { o[t] = a[t]; o[HDV + t] = b[t]; o[2 * HDV + t] = c[t]; }
}

// ---------------------------------------------------------------------------
// HMMA GEMM, 2-way split operands (unchanged from R8)
// ---------------------------------------------------------------------------
#define TILE_B   16384
#define STAGE_B  (4 * TILE_B)
#define SMEM_GEMM (2 * STAGE_B)

template <bool BF16>
__global__ __launch_bounds__(256) void mma_gemm(
    const void* __restrict__ A0v, const void* __restrict__ A1v,
    const void* __restrict__ B0v, const void* __restrict__ B1v,
    const float* __restrict__ bias, float* __restrict__ O,
    int N, int K)
{
    const float mergeScale = BF16 ? 1.0f : INV_SPLIT;
    extern __shared__ char smem[];
    const uint32_t sbase = smem_to_u32(smem);
    const int tid = threadIdx.x;
    const int lane = tid & 31, wid = tid >> 5;
    const int warp_m = wid & 3;
    const int warp_n = wid >> 2;
    const int m0 = blockIdx.x * 128, n0 = blockIdx.y * 128;
    const int NC = K >> 6;

    const uint16_t* src[4] = {
        (const uint16_t*)A0v + (size_t)m0 * K, (const uint16_t*)A1v + (size_t)m0 * K,
        (const uint16_t*)B0v + (size_t)n0 * K, (const uint16_t*)B1v + (size_t)n0 * K };

    const int lrow = tid >> 1;
    const int lhalf = tid & 1;

    float master[2][8][4];
#pragma unroll
    for (int a = 0; a < 2; a++)
#pragma unroll
        for (int b = 0; b < 8; b++)
#pragma unroll
            for (int c = 0; c < 4; c++) master[a][b][c] = 0.0f;

    auto load_stage = [&](int buf, int chunk) {
        const int kc = chunk << 6;
        const uint32_t sb = sbase + buf * STAGE_B;
#pragma unroll
        for (int t = 0; t < 4; t++) {
            const char* g = (const char*)(src[t] + (size_t)lrow * K + kc) + lhalf * 64;
            const uint32_t tb = sb + t * TILE_B;
#pragma unroll
            for (int i = 0; i < 4; i++) {
                uint32_t off = (uint32_t)(lrow * 128 + lhalf * 64 + i * 16);
                CP_ASYNC_CG(tb + SMEM_SWIZZLE_128B(off), g + i * 16);
            }
        }
    };

    load_stage(0, 0);
    CP_COMMIT();

    float chunk[2][8][4];

    for (int c = 0; c < NC; c++) {
        const int s = c & 1;
        if (c + 1 < NC) { load_stage(s ^ 1, c + 1); CP_COMMIT(); CP_WAIT_1(); }
        else            { CP_WAIT_0(); }
        __syncthreads();

        const uint32_t base = sbase + s * STAGE_B;

        // ---- pass A: mixed products (h*l + l*h) ----
#pragma unroll
        for (int a = 0; a < 2; a++)
#pragma unroll
            for (int b = 0; b < 8; b++)
#pragma unroll
                for (int cc = 0; cc < 4; cc++) chunk[a][b][cc] = 0.0f;

#pragma unroll
        for (int kk = 0; kk < 4; kk++) {
            uint32_t ah[2][4], al[2][4];
#pragma unroll
            for (int mt = 0; mt < 2; mt++) {
                int row = warp_m * 32 + mt * 16 + (lane & 15);
                int col = kk * 32 + ((lane >> 4) << 4);
                uint32_t off = SMEM_SWIZZLE_128B((uint32_t)(row * 128 + col));
                ldsm_x4(ah[mt], base + off);
                ldsm_x4(al[mt], base + TILE_B + off);
            }
#pragma unroll
            for (int p = 0; p < 4; p++) {
                int row = warp_n * 64 + p * 16 + (lane & 7) + (((lane >> 4) & 1) << 3);
                int col = kk * 32 + (((lane >> 3) & 1) << 4);
                uint32_t off = SMEM_SWIZZLE_128B((uint32_t)(row * 128 + col));
                uint32_t bh[4], bl[4];
                ldsm_x4(bh, base + 2 * TILE_B + off);
                ldsm_x4(bl, base + 3 * TILE_B + off);
#pragma unroll
                for (int mt = 0; mt < 2; mt++)
#pragma unroll
                    for (int n2 = 0; n2 < 2; n2++) {
                        mma_16<BF16>(chunk[mt][2 * p + n2], ah[mt], bl[2 * n2], bl[2 * n2 + 1]);
                        mma_16<BF16>(chunk[mt][2 * p + n2], al[mt], bh[2 * n2], bh[2 * n2 + 1]);
                    }
            }
        }
#pragma unroll
        for (int a = 0; a < 2; a++)
#pragma unroll
            for (int b = 0; b < 8; b++)
#pragma unroll
                for (int cc = 0; cc < 4; cc++)
                    master[a][b][cc] = fmaf(chunk[a][b][cc], mergeScale, master[a][b][cc]);

        // ---- pass B: h*h ----
#pragma unroll
        for (int a = 0; a < 2; a++)
#pragma unroll
            for (int b = 0; b < 8; b++)
#pragma unroll
                for (int cc = 0; cc < 4; cc++) chunk[a][b][cc] = 0.0f;

#pragma unroll
        for (int kk = 0; kk < 4; kk++) {
            uint32_t ah[2][4];
#pragma unroll
            for (int mt = 0; mt < 2; mt++) {
                int row = warp_m * 32 + mt * 16 + (lane & 15);
                int col = kk * 32 + ((lane >> 4) << 4);
                uint32_t off = SMEM_SWIZZLE_128B((uint32_t)(row * 128 + col));
                ldsm_x4(ah[mt], base + off);
            }
#pragma unroll
            for (int p = 0; p < 4; p++) {
                int row = warp_n * 64 + p * 16 + (lane & 7) + (((lane >> 4) & 1) << 3);
                int col = kk * 32 + (((lane >> 3) & 1) << 4);
                uint32_t off = SMEM_SWIZZLE_128B((uint32_t)(row * 128 + col));
                uint32_t bh[4];
                ldsm_x4(bh, base + 2 * TILE_B + off);
#pragma unroll
                for (int mt = 0; mt < 2; mt++)
#pragma unroll
                    for (int n2 = 0; n2 < 2; n2++)
                        mma_16<BF16>(chunk[mt][2 * p + n2], ah[mt], bh[2 * n2], bh[2 * n2 + 1]);
            }
        }
#pragma unroll
        for (int a = 0; a < 2; a++)
#pragma unroll
            for (int b = 0; b < 8; b++)
#pragma unroll
                for (int cc = 0; cc < 4; cc++) master[a][b][cc] += chunk[a][b][cc];

        __syncthreads();
    }

    // ---- epilogue ----
    float2 bcol[8];
#pragma unroll
    for (int nt = 0; nt < 8; nt++) {
        int cbase = n0 + warp_n * 64 + nt * 8 + (lane & 3) * 2;
        bcol[nt].x = __ldg(bias + cbase);
        bcol[nt].y = __ldg(bias + cbase + 1);
    }
#pragma unroll
    for (int mt = 0; mt < 2; mt++) {
        int r0 = m0 + warp_m * 32 + mt * 16 + (lane >> 2);
#pragma unroll
        for (int nt = 0; nt < 8; nt++) {
            int cbase = n0 + warp_n * 64 + nt * 8 + (lane & 3) * 2;
            float2 v0 = { master[mt][nt][0] + bcol[nt].x, master[mt][nt][1] + bcol[nt].y };
            float2 v1 = { master[mt][nt][2] + bcol[nt].x, master[mt][nt][3] + bcol[nt].y };
            *reinterpret_cast<float2*>(O + (size_t)r0 * N + cbase) = v0;
            *reinterpret_cast<float2*>(O + (size_t)(r0 + 8) * N + cbase) = v1;
        }
    }
}

// ---------------------------------------------------------------------------
// Gram kernel: per (batch, chunk): Gkk[u][t]=k_u.k_t, Gqk[u][t]=k_u.q_t.
// One block per chunk (1024 blocks), thread = (u,t).
// ---------------------------------------------------------------------------
__global__ __launch_bounds__(256) void gram_kernel(
    const float* __restrict__ qkv, float* __restrict__ G)
{
    const int blk = blockIdx.x;               // b*NCHUNK + c
    const int b = blk >> 7, c = blk & (NCHUNK - 1);
    const int u = threadIdx.x >> 4, t = threadIdx.x & 15;
    const float* basep = qkv + ((size_t)b * SS + c * SCAN_CH) * NQKV;
    const float4* ku = (const float4*)(basep + u * NQKV + 128);
    const float4* kt = (const float4*)(basep + t * NQKV + 128);
    const float4* qt = (const float4*)(basep + t * NQKV);
    float skk = 0.0f, sqk = 0.0f;
#pragma unroll 8
    for (int j = 0; j < 32; j++) {
        float4 a = __ldg(ku + j), bk = __ldg(kt + j), bq = __ldg(qt + j);
        skk += a.x * bk.x + a.y * bk.y + a.z * bk.z + a.w * bk.w;
        sqk += a.x * bq.x + a.y * bq.y + a.z * bq.z + a.w * bq.w;
    }
    float* go = G + (size_t)blk * 512;
    go[u * 16 + t] = skk;
    go[256 + u * 16 + t] = sqk;
}

// ---------------------------------------------------------------------------
// Delta-rule scan v3: CHUNKED delta rule (C=16). Per chunk with frozen W0:
//   e_t = lr*(W0.k_t - sum_{u<t} e_u*Gkk[u][t] - v_t)
//   y_t = W0.q_t - sum_{u<t} e_u*Gqk[u][t]
//   W  <- W0 - sum_u e_u (x) k_u
// W0 dots are parallel (pipelined reduces); only the C^2/2 scalar triangular
// recursion is serial (redundant in all lanes; register arrays, unrolled).
// ---------------------------------------------------------------------------
#define QKV_F   (SCAN_CH * NQKV)             // 6144 floats
#define STAGE_F (QKV_F + 512)                // + gram
#define SCAN_SMEM (2 * STAGE_F * 4)          // 53248 bytes

__global__ __launch_bounds__(256) void titan_scan(
    const float* __restrict__ qkv, const float* __restrict__ G,
    const float* __restrict__ state, const float* __restrict__ lr_ptr,
    float* __restrict__ ys, float* __restrict__ wfin)
{
    extern __shared__ float smemf[];
    const int tid  = threadIdx.x;
    const int warp = tid >> 5;
    const int lane = tid & 31;
    const int b    = blockIdx.x >> 4;
    const int i    = ((blockIdx.x & 15) << 3) + warp;

    const float lr = *lr_ptr;
    const float* base  = qkv + (size_t)b * SS * NQKV;
    const float* gbase = G + (size_t)b * NCHUNK * 512;
    float* yb = ys + (size_t)b * SS * HDV + i;

    const uint32_t s0 = smem_to_u32(smemf);
    auto stage = [&](int c) {
        if (c < NCHUNK) {
            const char* g = (const char*)(base + (size_t)c * QKV_F);
            const uint32_t sb = s0 + (uint32_t)(c & 1) * (STAGE_F * 4);
#pragma unroll
            for (int it = 0; it < 6; it++) {
                int idx = tid + it * 256;
                CP_ASYNC_CG(sb + idx * 16, g + idx * 16);
            }
            if (tid < 128)
                CP_ASYNC_CG(sb + QKV_F * 4 + tid * 16,
                            (const char*)(gbase + (size_t)c * 512) + tid * 16);
        }
    };
    stage(0); CP_COMMIT();
    stage(1); CP_COMMIT();

    float4 w4 = *reinterpret_cast<const float4*>(
        state + ((size_t)b * HDV + i) * HDV + lane * 4);

    for (int c = 0; c < NCHUNK; c++) {
        CP_WAIT_1();
        __syncthreads();
        const float* sb  = smemf + (c & 1) * STAGE_F;
        const float* gkk = sb + QKV_F;
        const float* gqk = gkk + 256;

        float Bv[SCAN_CH], e[SCAN_CH];
        float Asel = 0.0f;

        // ---- P1: parallel W0 dots, pipelined joint reduces ----
#pragma unroll
        for (int t = 0; t < SCAN_CH; t++) {
            const float* row = sb + t * NQKV;
            float4 q = *reinterpret_cast<const float4*>(row + lane * 4);
            float4 k = *reinterpret_cast<const float4*>(row + 128 + lane * 4);
            float a  = w4.x * q.x + w4.y * q.y + w4.z * q.z + w4.w * q.w;
            float bb = w4.x * k.x + w4.y * k.y + w4.z * k.z + w4.w * k.w;
#pragma unroll
            for (int o = 16; o > 0; o >>= 1) {
                a  += __shfl_xor_sync(0xffffffffu, a,  o);
                bb += __shfl_xor_sync(0xffffffffu, bb, o);
            }
            Bv[t] = bb;
            if (lane == t) Asel = a;
        }

        // ---- P2: serial triangular recursion (redundant in all lanes) ----
#pragma unroll
        for (int t = 0; t < SCAN_CH; t++) {
            float acc = Bv[t];
#pragma unroll
            for (int u = 0; u < SCAN_CH; u++)
                if (u < t) acc = fmaf(-e[u], gkk[u * 16 + t], acc);
            e[t] = lr * (acc - sb[t * NQKV + 256 + i]);
        }

        // ---- P3a: outputs (lane t < 16 computes y_t) ----
        if (lane < SCAN_CH) {
            float dq = Asel;
#pragma unroll
            for (int u = 0; u < SCAN_CH - 1; u++)
                if (u < lane) dq = fmaf(-e[u], gqk[u * 16 + lane], dq);
            yb[(size_t)(c * SCAN_CH + lane) * HDV] = dq;
        }

        // ---- P3b: W update ----
#pragma unroll
        for (int u = 0; u < SCAN_CH; u++) {
            float4 k = *reinterpret_cast<const float4*>(sb + u * NQKV + 128 + lane * 4);
            w4.x = fmaf(-e[u], k.x, w4.x);
            w4.y = fmaf(-e[u], k.y, w4.y);
            w4.z = fmaf(-e[u], k.z, w4.z);
            w4.w = fmaf(-e[u], k.w, w4.w);
        }

        __syncthreads();
        stage(c + 2); CP_COMMIT();
    }

    *reinterpret_cast<float4*>(wfin + ((size_t)b * HDV + i) * HDV + lane * 4) = w4;
}

// ---------------------------------------------------------------------------
// Launch
// ---------------------------------------------------------------------------
extern "C" void kernel_launch(void* const* d_in, const int* in_sizes, int n_in,
                              void* d_out, int out_size)
{
    const float* x     = (const float*)d_in[0];
    const float* state = (const float*)d_in[1];
    const float* Wq    = (const float*)d_in[2];
    const float* bq    = (const float*)d_in[3];
    const float* Wk    = (const float*)d_in[4];
    const float* bk    = (const float*)d_in[5];
    const float* Wv    = (const float*)d_in[6];
    const float* bv    = (const float*)d_in[7];
    const float* Wo    = (const float*)d_in[8];
    const float* bo    = (const float*)d_in[9];
    const float* lr    = (const float*)d_in[10];
    float* out = (float*)d_out;

    __half *xh, *xl, *wqkvh, *wqkvl;
    __nv_bfloat16 *yh, *yl, *woh, *wol;
    float *bqkv, *gqkv, *gy, *gws, *gG;
    cudaGetSymbolAddress((void**)&xh, g_xh);
    cudaGetSymbolAddress((void**)&xl, g_xl);
    cudaGetSymbolAddress((void**)&yh, g_yh);
    cudaGetSymbolAddress((void**)&yl, g_yl);
    cudaGetSymbolAddress((void**)&wqkvh, g_wqkvh);
    cudaGetSymbolAddress((void**)&wqkvl, g_wqkvl);
    cudaGetSymbolAddress((void**)&woh, g_woh);
    cudaGetSymbolAddress((void**)&wol, g_wol);
    cudaGetSymbolAddress((void**)&bqkv, g_bqkv);
    cudaGetSymbolAddress((void**)&gqkv, g_qkv);
    cudaGetSymbolAddress((void**)&gy, g_y);
    cudaGetSymbolAddress((void**)&gws, g_wfin_scratch);
    cudaGetSymbolAddress((void**)&gG, g_G);

    const size_t out_elems  = (size_t)BB * SS * DIMV;
    const size_t wfin_elems = (size_t)BB * HDV * HDV;
    float* wfin = ((size_t)out_size >= out_elems + wfin_elems)
                      ? (out + out_elems) : gws;

    cudaFuncSetAttribute(mma_gemm<false>, cudaFuncAttributeMaxDynamicSharedMemorySize, SMEM_GEMM);
    cudaFuncSetAttribute(mma_gemm<true>,  cudaFuncAttributeMaxDynamicSharedMemorySize, SMEM_GEMM);
    cudaFuncSetAttribute(titan_scan,      cudaFuncAttributeMaxDynamicSharedMemorySize, SCAN_SMEM);

    // 1) prep
    {
        int n4 = MTOK * DIMV / 4;
        split2f_kernel<<<(n4 + 255) / 256, 256>>>(x, xh, xl, n4);
        int kn = DIMV * HDV;
        transpose_split2f_kernel<<<(kn + 255) / 256, 256>>>(
            Wq, wqkvh + 0 * HDV * DIMV, wqkvl + 0 * HDV * DIMV, DIMV, HDV);
        transpose_split2f_kernel<<<(kn + 255) / 256, 256>>>(
            Wk, wqkvh + 1 * HDV * DIMV, wqkvl + 1 * HDV * DIMV, DIMV, HDV);
        transpose_split2f_kernel<<<(kn + 255) / 256, 256>>>(
            Wv, wqkvh + 2 * HDV * DIMV, wqkvl + 2 * HDV * DIMV, DIMV, HDV);
        transpose_split2b_kernel<<<(kn + 255) / 256, 256>>>(Wo, woh, wol, HDV, DIMV);
        concat_bias_kernel<<<1, 128>>>(bq, bk, bv, bqkv);
    }

    // 2) fused QKV projection (fp16 scaled split): [16384,2048] @ [2048,384]
    mma_gemm<false><<<dim3(MTOK / 128, NQKV / 128), 256, SMEM_GEMM>>>(
        xh, xl, wqkvh, wqkvl, bqkv, gqkv, NQKV, DIMV);

    // 3) gram precompute + chunked delta-rule scan
    gram_kernel<<<BB * NCHUNK, 256>>>(gqkv, gG);
    titan_scan<<<128, 256, SCAN_SMEM>>>(gqkv, gG, state, lr, gy, wfin);

    // 4) bf16-split y; output projection [16384,128] @ [128,2048]
    {
        int n4 = MTOK * HDV / 4;
        split2b_kernel<<<(n4 + 255) / 256, 256>>>(gy, yh, yl, n4);
    }
    mma_gemm<true><<<dim3(MTOK / 128, DIMV / 128), 256, SMEM_GEMM>>>(
        yh, yl, woh, wol, bo, out, DIMV, HDV);
}